// round 1
// baseline (speedup 1.0000x reference)
#include <cuda_runtime.h>
#include <cuda_bf16.h>
#include <cstdint>

#define TOKENS 4096
#define HIDDEN 2048
#define INTER  768
#define NEXP   64
#define TOPK   8
#define NPAIRS (TOKENS*TOPK)   // 32768
#define MCAP   2048            // per-expert row cap (expected max ~590)

// ---------------- device scratch (no allocations allowed) ----------------
__device__ int   g_counts[NEXP];
__device__ int   g_offsets[NEXP+1];
__device__ int   g_cursor[NEXP];
__device__ int   g_pair_e[NPAIRS];
__device__ float g_pair_w[NPAIRS];
__device__ int   g_row_token[NPAIRS];
__device__ float g_row_weight[NPAIRS];
__device__ float g_act[(size_t)NPAIRS * INTER];   // 96 MB swiglu output

// ---------------- small helpers ----------------
__device__ __forceinline__ uint32_t f2tf(float x) {
    uint32_t r;
    asm("cvt.rna.tf32.f32 %0, %1;" : "=r"(r) : "f"(x));
    return r;
}

#define MMA_TF32(c, a, b)                                                     \
    asm volatile(                                                             \
        "mma.sync.aligned.m16n8k8.row.col.f32.tf32.tf32.f32 "                 \
        "{%0,%1,%2,%3},{%4,%5,%6,%7},{%8,%9},{%0,%1,%2,%3};"                  \
        : "+f"((c)[0]), "+f"((c)[1]), "+f"((c)[2]), "+f"((c)[3])              \
        : "r"((a)[0]), "r"((a)[1]), "r"((a)[2]), "r"((a)[3]),                 \
          "r"((b)[0]), "r"((b)[1]))

#define CP16(dst_u32, src_ptr)                                                \
    asm volatile("cp.async.cg.shared.global [%0], [%1], 16;\n"                \
                 :: "r"(dst_u32), "l"(src_ptr))
#define CP_COMMIT asm volatile("cp.async.commit_group;\n")
#define CP_WAIT(n) asm volatile("cp.async.wait_group %0;\n" :: "n"(n))

__device__ __forceinline__ uint32_t smem_u32(const void* p) {
    return (uint32_t)__cvta_generic_to_shared(p);
}

// ---------------- kernel 0: zero output + counters ----------------
__global__ void zero_kernel(float4* __restrict__ out) {
    size_t i = (size_t)blockIdx.x * blockDim.x + threadIdx.x;
    out[i] = make_float4(0.f, 0.f, 0.f, 0.f);
    if (blockIdx.x == 0 && threadIdx.x < NEXP) g_counts[threadIdx.x] = 0;
}

// ---------------- kernel 1: top-8 routing + softmax ----------------
__global__ void route_kernel(const float* __restrict__ logits) {
    int t = blockIdx.x * blockDim.x + threadIdx.x;
    if (t >= TOKENS) return;
    float l[NEXP];
    const float* lp = logits + (size_t)t * NEXP;
#pragma unroll
    for (int i = 0; i < NEXP; ++i) l[i] = lp[i];

    float val[TOPK]; int sel[TOPK];
#pragma unroll
    for (int k = 0; k < TOPK; ++k) {
        float best = -1e30f; int bi = 0;
#pragma unroll
        for (int i = 0; i < NEXP; ++i) {
            if (l[i] > best) { best = l[i]; bi = i; }
        }
        val[k] = best; sel[k] = bi; l[bi] = -1e30f;
    }
    float m = val[0], s = 0.f, w[TOPK];
#pragma unroll
    for (int k = 0; k < TOPK; ++k) { w[k] = __expf(val[k] - m); s += w[k]; }
    float inv = 1.f / s;
#pragma unroll
    for (int k = 0; k < TOPK; ++k) {
        int e = sel[k];
        g_pair_e[t * TOPK + k] = e;
        g_pair_w[t * TOPK + k] = w[k] * inv;
        atomicAdd(&g_counts[e], 1);
    }
}

// ---------------- kernel 2: 64-bin prefix sum ----------------
__global__ void scan_kernel() {
    if (threadIdx.x == 0) {
        int acc = 0;
        for (int e = 0; e < NEXP; ++e) {
            g_offsets[e] = acc;
            g_cursor[e]  = acc;
            acc += g_counts[e];
        }
        g_offsets[NEXP] = acc;
    }
}

// ---------------- kernel 3: scatter pairs into expert-sorted order --------
__global__ void scatter_kernel() {
    int p = blockIdx.x * blockDim.x + threadIdx.x;
    if (p >= NPAIRS) return;
    int e = g_pair_e[p];
    int slot = atomicAdd(&g_cursor[e], 1);
    g_row_token[slot]  = p >> 3;          // token id
    g_row_weight[slot] = g_pair_w[p];
}

// ---------------- kernel 4: grouped GEMM1 (gate||up, swiglu) --------------
// C[cnt,768] per expert; BM=128 BN=64 BK=16; 8 warps (4x2), warp tile 32x32,
// dual accumulators (gate & up share the A tile).
__global__ void __launch_bounds__(256, 2)
gemm1_kernel(const float* __restrict__ hidden,
             const float* __restrict__ gate_w,
             const float* __restrict__ up_w) {
    int e   = blockIdx.z;
    int off = g_offsets[e];
    int cnt = g_offsets[e + 1] - off;
    int m0  = blockIdx.x * 128;
    if (m0 >= cnt) return;
    int n0  = blockIdx.y * 64;

    __shared__ float sA [2][128][20];
    __shared__ float sBg[2][16][68];
    __shared__ float sBu[2][16][68];

    int tid = threadIdx.x;
    const size_t wbase = (size_t)e * HIDDEN * INTER;
    int maxslot = off + cnt - 1;

    // A gather assignments: 512 16B chunks / 256 threads = 2 each
    const float* asrc[2];
    int arowi[2], akc[2];
#pragma unroll
    for (int j = 0; j < 2; ++j) {
        int c = tid + j * 256;
        int row = c >> 2, kc = (c & 3) << 2;
        int slot = off + m0 + row;
        if (slot > maxslot) slot = maxslot;
        int tok = g_row_token[slot];
        asrc[j] = hidden + (size_t)tok * HIDDEN + kc;
        arowi[j] = row; akc[j] = kc;
    }
    // B assignments: 256 chunks each for gate / up -> 1 per thread
    int bkr = tid >> 4, bnc = (tid & 15) << 2;
    const float* gsrc = gate_w + wbase + (size_t)bkr * INTER + n0 + bnc;
    const float* usrc = up_w   + wbase + (size_t)bkr * INTER + n0 + bnc;

    auto load_tile = [&](int s, int k0) {
#pragma unroll
        for (int j = 0; j < 2; ++j)
            CP16(smem_u32(&sA[s][arowi[j]][akc[j]]), asrc[j] + k0);
        CP16(smem_u32(&sBg[s][bkr][bnc]), gsrc + (size_t)k0 * INTER);
        CP16(smem_u32(&sBu[s][bkr][bnc]), usrc + (size_t)k0 * INTER);
    };

    float cg[2][4][4] = {}, cu[2][4][4] = {};
    int warp = tid >> 5, lane = tid & 31;
    int wm = warp >> 1, wn = warp & 1;
    int gid = lane >> 2, tig = lane & 3;

    load_tile(0, 0); CP_COMMIT;
    const int KT = HIDDEN / 16;
    for (int kt = 0; kt < KT; ++kt) {
        int s = kt & 1;
        if (kt + 1 < KT) { load_tile(s ^ 1, (kt + 1) * 16); CP_COMMIT; CP_WAIT(1); }
        else             { CP_WAIT(0); }
        __syncthreads();
#pragma unroll
        for (int ks = 0; ks < 2; ++ks) {
            int k8 = ks * 8;
            uint32_t af[2][4];
#pragma unroll
            for (int mt = 0; mt < 2; ++mt) {
                int r = wm * 32 + mt * 16;
                af[mt][0] = f2tf(sA[s][r + gid    ][k8 + tig    ]);
                af[mt][1] = f2tf(sA[s][r + gid + 8][k8 + tig    ]);
                af[mt][2] = f2tf(sA[s][r + gid    ][k8 + tig + 4]);
                af[mt][3] = f2tf(sA[s][r + gid + 8][k8 + tig + 4]);
            }
            uint32_t bg[4][2], bu[4][2];
#pragma unroll
            for (int nt = 0; nt < 4; ++nt) {
                int cix = wn * 32 + nt * 8 + gid;
                bg[nt][0] = f2tf(sBg[s][k8 + tig    ][cix]);
                bg[nt][1] = f2tf(sBg[s][k8 + tig + 4][cix]);
                bu[nt][0] = f2tf(sBu[s][k8 + tig    ][cix]);
                bu[nt][1] = f2tf(sBu[s][k8 + tig + 4][cix]);
            }
#pragma unroll
            for (int mt = 0; mt < 2; ++mt)
#pragma unroll
                for (int nt = 0; nt < 4; ++nt) {
                    MMA_TF32(cg[mt][nt], af[mt], bg[nt]);
                    MMA_TF32(cu[mt][nt], af[mt], bu[nt]);
                }
        }
        __syncthreads();
    }

    // swiglu epilogue -> g_act
#pragma unroll
    for (int mt = 0; mt < 2; ++mt) {
#pragma unroll
        for (int i = 0; i < 4; ++i) {
            int row  = wm * 32 + mt * 16 + gid + ((i >> 1) << 3);
            int srow = m0 + row;
            if (srow >= cnt) continue;
            size_t base = (size_t)(off + srow) * INTER + n0 + wn * 32;
#pragma unroll
            for (int nt = 0; nt < 4; ++nt) {
                float g = cg[mt][nt][i], u = cu[mt][nt][i];
                float a = g / (1.f + __expf(-g)) * u;   // silu(g)*u
                g_act[base + nt * 8 + 2 * tig + (i & 1)] = a;
            }
        }
    }
}

// ---------------- kernel 5: grouped GEMM2 (down proj + weighted combine) --
// BM=128 BN=128 BK=16; 8 warps (4x2), warp tile 32x64.
__global__ void __launch_bounds__(256, 2)
gemm2_kernel(const float* __restrict__ down_w, float* __restrict__ out) {
    int e   = blockIdx.z;
    int off = g_offsets[e];
    int cnt = g_offsets[e + 1] - off;
    int m0  = blockIdx.x * 128;
    if (m0 >= cnt) return;
    int n0  = blockIdx.y * 128;

    __shared__ float sA[2][128][20];
    __shared__ float sB[2][16][132];

    int tid = threadIdx.x;
    const size_t wbase = (size_t)e * INTER * HIDDEN;

    // A: rows are contiguous in g_act (already expert-sorted)
    const float* asrc[2]; int arowi[2], akc[2];
#pragma unroll
    for (int j = 0; j < 2; ++j) {
        int c = tid + j * 256;
        int row = c >> 2, kc = (c & 3) << 2;
        int ar = off + m0 + row;
        if (ar > NPAIRS - 1) ar = NPAIRS - 1;
        asrc[j] = g_act + (size_t)ar * INTER + kc;
        arowi[j] = row; akc[j] = kc;
    }
    // B: 512 chunks -> 2 per thread
    const float* bsrc[2]; int bkri[2], bnci[2];
#pragma unroll
    for (int j = 0; j < 2; ++j) {
        int c = tid + j * 256;
        int kr = c >> 5, nc = (c & 31) << 2;
        bsrc[j] = down_w + wbase + (size_t)kr * HIDDEN + n0 + nc;
        bkri[j] = kr; bnci[j] = nc;
    }

    auto load_tile = [&](int s, int k0) {
#pragma unroll
        for (int j = 0; j < 2; ++j)
            CP16(smem_u32(&sA[s][arowi[j]][akc[j]]), asrc[j] + k0);
#pragma unroll
        for (int j = 0; j < 2; ++j)
            CP16(smem_u32(&sB[s][bkri[j]][bnci[j]]), bsrc[j] + (size_t)k0 * HIDDEN);
    };

    float acc[2][8][4] = {};
    int warp = tid >> 5, lane = tid & 31;
    int wm = warp >> 1, wn = warp & 1;
    int gid = lane >> 2, tig = lane & 3;

    load_tile(0, 0); CP_COMMIT;
    const int KT = INTER / 16;
    for (int kt = 0; kt < KT; ++kt) {
        int s = kt & 1;
        if (kt + 1 < KT) { load_tile(s ^ 1, (kt + 1) * 16); CP_COMMIT; CP_WAIT(1); }
        else             { CP_WAIT(0); }
        __syncthreads();
#pragma unroll
        for (int ks = 0; ks < 2; ++ks) {
            int k8 = ks * 8;
            uint32_t af[2][4];
#pragma unroll
            for (int mt = 0; mt < 2; ++mt) {
                int r = wm * 32 + mt * 16;
                af[mt][0] = f2tf(sA[s][r + gid    ][k8 + tig    ]);
                af[mt][1] = f2tf(sA[s][r + gid + 8][k8 + tig    ]);
                af[mt][2] = f2tf(sA[s][r + gid    ][k8 + tig + 4]);
                af[mt][3] = f2tf(sA[s][r + gid + 8][k8 + tig + 4]);
            }
            uint32_t bf[8][2];
#pragma unroll
            for (int nt = 0; nt < 8; ++nt) {
                int cix = wn * 64 + nt * 8 + gid;
                bf[nt][0] = f2tf(sB[s][k8 + tig    ][cix]);
                bf[nt][1] = f2tf(sB[s][k8 + tig + 4][cix]);
            }
#pragma unroll
            for (int mt = 0; mt < 2; ++mt)
#pragma unroll
                for (int nt = 0; nt < 8; ++nt)
                    MMA_TF32(acc[mt][nt], af[mt], bf[nt]);
        }
        __syncthreads();
    }

    // epilogue: weight-scale + atomic combine into out[token]
#pragma unroll
    for (int mt = 0; mt < 2; ++mt) {
#pragma unroll
        for (int i = 0; i < 4; ++i) {
            int row  = wm * 32 + mt * 16 + gid + ((i >> 1) << 3);
            int srow = m0 + row;
            if (srow >= cnt) continue;
            int slot = off + srow;
            int t    = g_row_token[slot];
            float w  = g_row_weight[slot];
            float* orow = out + (size_t)t * HIDDEN + n0 + wn * 64;
#pragma unroll
            for (int nt = 0; nt < 8; ++nt)
                atomicAdd(&orow[nt * 8 + 2 * tig + (i & 1)], acc[mt][nt][i] * w);
        }
    }
}

// ---------------- launch ----------------
extern "C" void kernel_launch(void* const* d_in, const int* in_sizes, int n_in,
                              void* d_out, int out_size) {
    const float* hidden = (const float*)d_in[0];
    const float* logits = (const float*)d_in[1];
    const float* gate   = (const float*)d_in[2];
    const float* up     = (const float*)d_in[3];
    const float* down   = (const float*)d_in[4];
    float* out = (float*)d_out;

    zero_kernel   <<<4096, 512>>>((float4*)out);          // 8M floats exactly
    route_kernel  <<<TOKENS / 256, 256>>>(logits);
    scan_kernel   <<<1, 32>>>();
    scatter_kernel<<<NPAIRS / 256, 256>>>();
    gemm1_kernel  <<<dim3(MCAP / 128, INTER / 64, NEXP), 256>>>(hidden, gate, up);
    gemm2_kernel  <<<dim3(MCAP / 128, HIDDEN / 128, NEXP), 256>>>(down, out);
}

// round 2
// speedup vs baseline: 1.0022x; 1.0022x over previous
#include <cuda_runtime.h>
#include <cuda_bf16.h>
#include <cstdint>

#define TOKENS 4096
#define HIDDEN 2048
#define INTER  768
#define NEXP   64
#define TOPK   8
#define NPAIRS (TOKENS*TOPK)   // 32768
#define MCAP   2048            // per-expert row cap (expected max ~590)

// ---------------- device scratch (no allocations allowed) ----------------
__device__ int   g_counts[NEXP];
__device__ int   g_offsets[NEXP+1];
__device__ int   g_cursor[NEXP];
__device__ int   g_pair_e[NPAIRS];
__device__ float g_pair_w[NPAIRS];
__device__ int   g_row_token[NPAIRS];
__device__ float g_row_weight[NPAIRS];
__device__ float g_act[(size_t)NPAIRS * INTER];   // 96 MB swiglu output

// ---------------- small helpers ----------------
__device__ __forceinline__ uint32_t f2tf(float x) {
    uint32_t r;
    asm("cvt.rna.tf32.f32 %0, %1;" : "=r"(r) : "f"(x));
    return r;
}

#define MMA_TF32(c, a, b)                                                     \
    asm volatile(                                                             \
        "mma.sync.aligned.m16n8k8.row.col.f32.tf32.tf32.f32 "                 \
        "{%0,%1,%2,%3},{%4,%5,%6,%7},{%8,%9},{%0,%1,%2,%3};"                  \
        : "+f"((c)[0]), "+f"((c)[1]), "+f"((c)[2]), "+f"((c)[3])              \
        : "r"((a)[0]), "r"((a)[1]), "r"((a)[2]), "r"((a)[3]),                 \
          "r"((b)[0]), "r"((b)[1]))

#define CP16(dst_u32, src_ptr)                                                \
    asm volatile("cp.async.cg.shared.global [%0], [%1], 16;\n"                \
                 :: "r"(dst_u32), "l"(src_ptr))
#define CP_COMMIT asm volatile("cp.async.commit_group;\n")
#define CP_WAIT(n) asm volatile("cp.async.wait_group %0;\n" :: "n"(n))

__device__ __forceinline__ uint32_t smem_u32(const void* p) {
    return (uint32_t)__cvta_generic_to_shared(p);
}

// ---------------- kernel 0: zero output + counters ----------------
__global__ void zero_kernel(float4* __restrict__ out) {
    size_t i = (size_t)blockIdx.x * blockDim.x + threadIdx.x;
    out[i] = make_float4(0.f, 0.f, 0.f, 0.f);
    if (blockIdx.x == 0 && threadIdx.x < NEXP) g_counts[threadIdx.x] = 0;
}

// ---------------- kernel 1: top-8 routing + softmax ----------------
__global__ void route_kernel(const float* __restrict__ logits) {
    int t = blockIdx.x * blockDim.x + threadIdx.x;
    if (t >= TOKENS) return;
    float l[NEXP];
    const float* lp = logits + (size_t)t * NEXP;
#pragma unroll
    for (int i = 0; i < NEXP; ++i) l[i] = lp[i];

    float val[TOPK]; int sel[TOPK];
#pragma unroll
    for (int k = 0; k < TOPK; ++k) {
        float best = -1e30f; int bi = 0;
#pragma unroll
        for (int i = 0; i < NEXP; ++i) {
            if (l[i] > best) { best = l[i]; bi = i; }
        }
        val[k] = best; sel[k] = bi; l[bi] = -1e30f;
    }
    float m = val[0], s = 0.f, w[TOPK];
#pragma unroll
    for (int k = 0; k < TOPK; ++k) { w[k] = __expf(val[k] - m); s += w[k]; }
    float inv = 1.f / s;
#pragma unroll
    for (int k = 0; k < TOPK; ++k) {
        int e = sel[k];
        g_pair_e[t * TOPK + k] = e;
        g_pair_w[t * TOPK + k] = w[k] * inv;
        atomicAdd(&g_counts[e], 1);
    }
}

// ---------------- kernel 2: 64-bin prefix sum ----------------
__global__ void scan_kernel() {
    if (threadIdx.x == 0) {
        int acc = 0;
        for (int e = 0; e < NEXP; ++e) {
            g_offsets[e] = acc;
            g_cursor[e]  = acc;
            acc += g_counts[e];
        }
        g_offsets[NEXP] = acc;
    }
}

// ---------------- kernel 3: scatter pairs into expert-sorted order --------
__global__ void scatter_kernel() {
    int p = blockIdx.x * blockDim.x + threadIdx.x;
    if (p >= NPAIRS) return;
    int e = g_pair_e[p];
    int slot = atomicAdd(&g_cursor[e], 1);
    g_row_token[slot]  = p >> 3;          // token id
    g_row_weight[slot] = g_pair_w[p];
}

// ---------------- kernel 4: grouped GEMM1 (gate||up, swiglu) --------------
// C[cnt,768] per expert; BM=128 BN=64 BK=16; 8 warps (4x2), warp tile 32x32,
// dual accumulators (gate & up share the A tile).
__global__ void __launch_bounds__(256, 2)
gemm1_kernel(const float* __restrict__ hidden,
             const float* __restrict__ gate_w,
             const float* __restrict__ up_w) {
    int e   = blockIdx.z;
    int off = g_offsets[e];
    int cnt = g_offsets[e + 1] - off;
    int m0  = blockIdx.x * 128;
    if (m0 >= cnt) return;
    int n0  = blockIdx.y * 64;

    __shared__ float sA [2][128][20];
    __shared__ float sBg[2][16][68];
    __shared__ float sBu[2][16][68];

    int tid = threadIdx.x;
    const size_t wbase = (size_t)e * HIDDEN * INTER;
    int maxslot = off + cnt - 1;

    // A gather assignments: 512 16B chunks / 256 threads = 2 each
    const float* asrc[2];
    int arowi[2], akc[2];
#pragma unroll
    for (int j = 0; j < 2; ++j) {
        int c = tid + j * 256;
        int row = c >> 2, kc = (c & 3) << 2;
        int slot = off + m0 + row;
        if (slot > maxslot) slot = maxslot;
        int tok = g_row_token[slot];
        asrc[j] = hidden + (size_t)tok * HIDDEN + kc;
        arowi[j] = row; akc[j] = kc;
    }
    // B assignments: 256 chunks each for gate / up -> 1 per thread
    int bkr = tid >> 4, bnc = (tid & 15) << 2;
    const float* gsrc = gate_w + wbase + (size_t)bkr * INTER + n0 + bnc;
    const float* usrc = up_w   + wbase + (size_t)bkr * INTER + n0 + bnc;

    auto load_tile = [&](int s, int k0) {
#pragma unroll
        for (int j = 0; j < 2; ++j)
            CP16(smem_u32(&sA[s][arowi[j]][akc[j]]), asrc[j] + k0);
        CP16(smem_u32(&sBg[s][bkr][bnc]), gsrc + (size_t)k0 * INTER);
        CP16(smem_u32(&sBu[s][bkr][bnc]), usrc + (size_t)k0 * INTER);
    };

    float cg[2][4][4] = {}, cu[2][4][4] = {};
    int warp = tid >> 5, lane = tid & 31;
    int wm = warp >> 1, wn = warp & 1;
    int gid = lane >> 2, tig = lane & 3;

    load_tile(0, 0); CP_COMMIT;
    const int KT = HIDDEN / 16;
    for (int kt = 0; kt < KT; ++kt) {
        int s = kt & 1;
        if (kt + 1 < KT) { load_tile(s ^ 1, (kt + 1) * 16); CP_COMMIT; CP_WAIT(1); }
        else             { CP_WAIT(0); }
        __syncthreads();
#pragma unroll
        for (int ks = 0; ks < 2; ++ks) {
            int k8 = ks * 8;
            uint32_t af[2][4];
#pragma unroll
            for (int mt = 0; mt < 2; ++mt) {
                int r = wm * 32 + mt * 16;
                af[mt][0] = f2tf(sA[s][r + gid    ][k8 + tig    ]);
                af[mt][1] = f2tf(sA[s][r + gid + 8][k8 + tig    ]);
                af[mt][2] = f2tf(sA[s][r + gid    ][k8 + tig + 4]);
                af[mt][3] = f2tf(sA[s][r + gid + 8][k8 + tig + 4]);
            }
            uint32_t bg[4][2], bu[4][2];
#pragma unroll
            for (int nt = 0; nt < 4; ++nt) {
                int cix = wn * 32 + nt * 8 + gid;
                bg[nt][0] = f2tf(sBg[s][k8 + tig    ][cix]);
                bg[nt][1] = f2tf(sBg[s][k8 + tig + 4][cix]);
                bu[nt][0] = f2tf(sBu[s][k8 + tig    ][cix]);
                bu[nt][1] = f2tf(sBu[s][k8 + tig + 4][cix]);
            }
#pragma unroll
            for (int mt = 0; mt < 2; ++mt)
#pragma unroll
                for (int nt = 0; nt < 4; ++nt) {
                    MMA_TF32(cg[mt][nt], af[mt], bg[nt]);
                    MMA_TF32(cu[mt][nt], af[mt], bu[nt]);
                }
        }
        __syncthreads();
    }

    // swiglu epilogue -> g_act
#pragma unroll
    for (int mt = 0; mt < 2; ++mt) {
#pragma unroll
        for (int i = 0; i < 4; ++i) {
            int row  = wm * 32 + mt * 16 + gid + ((i >> 1) << 3);
            int srow = m0 + row;
            if (srow >= cnt) continue;
            size_t base = (size_t)(off + srow) * INTER + n0 + wn * 32;
#pragma unroll
            for (int nt = 0; nt < 4; ++nt) {
                float g = cg[mt][nt][i], u = cu[mt][nt][i];
                float a = g / (1.f + __expf(-g)) * u;   // silu(g)*u
                g_act[base + nt * 8 + 2 * tig + (i & 1)] = a;
            }
        }
    }
}

// ---------------- kernel 5: grouped GEMM2 (down proj + weighted combine) --
// BM=128 BN=128 BK=16; 8 warps (4x2), warp tile 32x64.
__global__ void __launch_bounds__(256, 2)
gemm2_kernel(const float* __restrict__ down_w, float* __restrict__ out) {
    int e   = blockIdx.z;
    int off = g_offsets[e];
    int cnt = g_offsets[e + 1] - off;
    int m0  = blockIdx.x * 128;
    if (m0 >= cnt) return;
    int n0  = blockIdx.y * 128;

    __shared__ float sA[2][128][20];
    __shared__ float sB[2][16][132];

    int tid = threadIdx.x;
    const size_t wbase = (size_t)e * INTER * HIDDEN;

    // A: rows are contiguous in g_act (already expert-sorted)
    const float* asrc[2]; int arowi[2], akc[2];
#pragma unroll
    for (int j = 0; j < 2; ++j) {
        int c = tid + j * 256;
        int row = c >> 2, kc = (c & 3) << 2;
        int ar = off + m0 + row;
        if (ar > NPAIRS - 1) ar = NPAIRS - 1;
        asrc[j] = g_act + (size_t)ar * INTER + kc;
        arowi[j] = row; akc[j] = kc;
    }
    // B: 512 chunks -> 2 per thread
    const float* bsrc[2]; int bkri[2], bnci[2];
#pragma unroll
    for (int j = 0; j < 2; ++j) {
        int c = tid + j * 256;
        int kr = c >> 5, nc = (c & 31) << 2;
        bsrc[j] = down_w + wbase + (size_t)kr * HIDDEN + n0 + nc;
        bkri[j] = kr; bnci[j] = nc;
    }

    auto load_tile = [&](int s, int k0) {
#pragma unroll
        for (int j = 0; j < 2; ++j)
            CP16(smem_u32(&sA[s][arowi[j]][akc[j]]), asrc[j] + k0);
#pragma unroll
        for (int j = 0; j < 2; ++j)
            CP16(smem_u32(&sB[s][bkri[j]][bnci[j]]), bsrc[j] + (size_t)k0 * HIDDEN);
    };

    float acc[2][8][4] = {};
    int warp = tid >> 5, lane = tid & 31;
    int wm = warp >> 1, wn = warp & 1;
    int gid = lane >> 2, tig = lane & 3;

    load_tile(0, 0); CP_COMMIT;
    const int KT = INTER / 16;
    for (int kt = 0; kt < KT; ++kt) {
        int s = kt & 1;
        if (kt + 1 < KT) { load_tile(s ^ 1, (kt + 1) * 16); CP_COMMIT; CP_WAIT(1); }
        else             { CP_WAIT(0); }
        __syncthreads();
#pragma unroll
        for (int ks = 0; ks < 2; ++ks) {
            int k8 = ks * 8;
            uint32_t af[2][4];
#pragma unroll
            for (int mt = 0; mt < 2; ++mt) {
                int r = wm * 32 + mt * 16;
                af[mt][0] = f2tf(sA[s][r + gid    ][k8 + tig    ]);
                af[mt][1] = f2tf(sA[s][r + gid + 8][k8 + tig    ]);
                af[mt][2] = f2tf(sA[s][r + gid    ][k8 + tig + 4]);
                af[mt][3] = f2tf(sA[s][r + gid + 8][k8 + tig + 4]);
            }
            uint32_t bf[8][2];
#pragma unroll
            for (int nt = 0; nt < 8; ++nt) {
                int cix = wn * 64 + nt * 8 + gid;
                bf[nt][0] = f2tf(sB[s][k8 + tig    ][cix]);
                bf[nt][1] = f2tf(sB[s][k8 + tig + 4][cix]);
            }
#pragma unroll
            for (int mt = 0; mt < 2; ++mt)
#pragma unroll
                for (int nt = 0; nt < 8; ++nt)
                    MMA_TF32(acc[mt][nt], af[mt], bf[nt]);
        }
        __syncthreads();
    }

    // epilogue: weight-scale + atomic combine into out[token]
#pragma unroll
    for (int mt = 0; mt < 2; ++mt) {
#pragma unroll
        for (int i = 0; i < 4; ++i) {
            int row  = wm * 32 + mt * 16 + gid + ((i >> 1) << 3);
            int srow = m0 + row;
            if (srow >= cnt) continue;
            int slot = off + srow;
            int t    = g_row_token[slot];
            float w  = g_row_weight[slot];
            float* orow = out + (size_t)t * HIDDEN + n0 + wn * 64;
#pragma unroll
            for (int nt = 0; nt < 8; ++nt)
                atomicAdd(&orow[nt * 8 + 2 * tig + (i & 1)], acc[mt][nt][i] * w);
        }
    }
}

// ---------------- launch ----------------
extern "C" void kernel_launch(void* const* d_in, const int* in_sizes, int n_in,
                              void* d_out, int out_size) {
    const float* hidden = (const float*)d_in[0];
    const float* logits = (const float*)d_in[1];
    const float* gate   = (const float*)d_in[2];
    const float* up     = (const float*)d_in[3];
    const float* down   = (const float*)d_in[4];
    float* out = (float*)d_out;

    zero_kernel   <<<4096, 512>>>((float4*)out);          // 8M floats exactly
    route_kernel  <<<TOKENS / 256, 256>>>(logits);
    scan_kernel   <<<1, 32>>>();
    scatter_kernel<<<NPAIRS / 256, 256>>>();
    gemm1_kernel  <<<dim3(MCAP / 128, INTER / 64, NEXP), 256>>>(hidden, gate, up);
    gemm2_kernel  <<<dim3(MCAP / 128, HIDDEN / 128, NEXP), 256>>>(down, out);
}

// round 5
// speedup vs baseline: 1.2021x; 1.1994x over previous
#include <cuda_runtime.h>
#include <cstdint>

#if defined(__CUDA_ARCH_FEAT_SM103_ALL) || defined(__CUDA_ARCH_FEAT_SM100_ALL) || defined(__CUDA_ARCH_FEAT_SM101_ALL)
#define TC_OK 1
#endif

#define TOKENS 4096
#define HIDDEN 2048
#define INTER  768
#define NEXP   64
#define TOPK   8
#define NPAIRS (TOKENS*TOPK)
#define MCAP   2048
#define BK     32
#define STAGE  49152
#define KT1    (HIDDEN/BK)
#define KT2    (INTER/BK)
#define WSZ    100663296   // 64*2048*768

__device__ int   g_tc_ok;
__device__ int   g_ok1;
__device__ int   g_ok2;
__device__ int   g_counts[NEXP];
__device__ int   g_offsets[NEXP+1];
__device__ int   g_cursor[NEXP];
__device__ int   g_pair_e[NPAIRS];
__device__ float g_pair_w[NPAIRS];
__device__ int   g_row_token[NPAIRS];
__device__ float g_row_weight[NPAIRS];
__device__ int   g_s2p[NPAIRS];
__device__ float g_act[(size_t)NPAIRS * INTER];
__device__ float g_pout[(size_t)NPAIRS * HIDDEN];
__device__ float g_hid[(size_t)TOKENS * HIDDEN];
__device__ float g_wtg[WSZ];   // gate transposed [E][INTER][HIDDEN]
__device__ float g_wtu[WSZ];   // up   transposed [E][INTER][HIDDEN]
__device__ float g_wtd[WSZ];   // down transposed [E][HIDDEN][INTER]

__device__ __forceinline__ uint32_t smem_u32(const void* p) {
    return (uint32_t)__cvta_generic_to_shared(p);
}
__device__ __forceinline__ float f2tf(float x) {
    uint32_t r;
    asm("cvt.rna.tf32.f32 %0, %1;" : "=r"(r) : "f"(x));
    return __uint_as_float(r);
}
__device__ __forceinline__ uint32_t f2tfu(float x) {
    uint32_t r;
    asm("cvt.rna.tf32.f32 %0, %1;" : "=r"(r) : "f"(x));
    return r;
}
#define SW128(o) ((o) ^ (((o) >> 3) & 0x70))
#define CP16(d, s) asm volatile("cp.async.cg.shared.global [%0], [%1], 16;\n" :: "r"(d), "l"(s))
#define CP_COMMIT  asm volatile("cp.async.commit_group;\n")
#define CP_WAIT(n) asm volatile("cp.async.wait_group %0;\n" :: "n"(n))
#define MBAR_INIT(mb, c) asm volatile("mbarrier.init.shared.b64 [%0], %1;" :: "r"(mb), "r"(c) : "memory")
#define MBAR_WAIT(mb, ph)                                                     \
    asm volatile("{\n\t.reg .pred P1;\n\t"                                    \
        "WL_%=:\n\t"                                                          \
        "mbarrier.try_wait.parity.acquire.cta.shared::cta.b64 P1, [%0], %1, 0x989680;\n\t" \
        "@P1 bra.uni WD_%=;\n\t"                                              \
        "bra.uni WL_%=;\n\t"                                                  \
        "WD_%=:\n\t}" :: "r"(mb), "r"(ph) : "memory")

#ifdef TC_OK
#define TC_ALLOC(sm, n)  asm volatile("tcgen05.alloc.cta_group::1.sync.aligned.shared::cta.b32 [%0], %1;" :: "r"(sm), "r"(n) : "memory")
#define TC_DEALLOC(t, n) asm volatile("tcgen05.dealloc.cta_group::1.sync.aligned.b32 %0, %1;" :: "r"(t), "r"(n))
#define TC_RELINQ()      asm volatile("tcgen05.relinquish_alloc_permit.cta_group::1.sync.aligned;")
#define TC_COMMIT(mb)    asm volatile("tcgen05.commit.cta_group::1.mbarrier::arrive::one.shared::cluster.b64 [%0];" :: "r"(mb) : "memory")
#define TC_FENCE_AFTER() asm volatile("tcgen05.fence::after_thread_sync;" ::: "memory")
#define TC_WAIT_LD()     asm volatile("tcgen05.wait::ld.sync.aligned;" ::: "memory")
#define FENCE_ASYNC()    asm volatile("fence.proxy.async.shared::cta;" ::: "memory")
#define LDTM_X32(r, a)                                                        \
    asm volatile("tcgen05.ld.sync.aligned.32x32b.x32.b32 "                    \
        "{%0,%1,%2,%3,%4,%5,%6,%7,%8,%9,%10,%11,%12,%13,%14,%15,"             \
        "%16,%17,%18,%19,%20,%21,%22,%23,%24,%25,%26,%27,%28,%29,%30,%31},[%32];" \
        : "=r"((r)[0]),"=r"((r)[1]),"=r"((r)[2]),"=r"((r)[3]),                \
          "=r"((r)[4]),"=r"((r)[5]),"=r"((r)[6]),"=r"((r)[7]),                \
          "=r"((r)[8]),"=r"((r)[9]),"=r"((r)[10]),"=r"((r)[11]),              \
          "=r"((r)[12]),"=r"((r)[13]),"=r"((r)[14]),"=r"((r)[15]),            \
          "=r"((r)[16]),"=r"((r)[17]),"=r"((r)[18]),"=r"((r)[19]),            \
          "=r"((r)[20]),"=r"((r)[21]),"=r"((r)[22]),"=r"((r)[23]),            \
          "=r"((r)[24]),"=r"((r)[25]),"=r"((r)[26]),"=r"((r)[27]),            \
          "=r"((r)[28]),"=r"((r)[29]),"=r"((r)[30]),"=r"((r)[31]) : "r"(a))

__device__ __forceinline__ uint64_t desc_k(uint32_t a) {   // K-major SW128
    return (uint64_t(2) << 61) | (uint64_t(1) << 46) | (uint64_t(64) << 32) |
           (uint64_t(1) << 16) | ((uint64_t)(a >> 4) & 0x3FFF);
}
// d=f32, a=b=tf32 (fmt 2), no transpose, N=32, M=128
#define IDESC ((1u<<4)|(2u<<7)|(2u<<10)|(4u<<17)|(8u<<24))
__device__ __forceinline__ void mma32(uint32_t d, uint64_t ad, uint64_t bd, uint32_t acc) {
    asm volatile(
        "{\n\t.reg .pred p;\n\tsetp.ne.u32 p, %4, 0;\n\t"
        "tcgen05.mma.cta_group::1.kind::tf32 [%0], %1, %2, %3, {%5,%5,%5,%5}, p;\n\t}"
        :: "r"(d), "l"(ad), "l"(bd), "r"(IDESC), "r"(acc), "r"(0u) : "memory");
}
#endif

// ---------------- self-test values ----------------
__device__ __forceinline__ float tva(int m, int k) {
    return f2tf(0.01f * (float)((m * 7 + k * 13) % 31 - 15));
}
__device__ __forceinline__ float tvb(int n, int k) {
    return f2tf(0.02f * (float)((n * 5 + k * 3) % 29 - 14));
}

// tcgen05 self-test: 128x32x32 tf32 SS MMA vs direct FMA reference
__global__ void selftest_kernel() {
#ifdef TC_OK
    __shared__ __align__(1024) float sma[4096];   // 128 rows x 128B
    __shared__ __align__(1024) float smb[1024];   // 32 rows x 128B
    __shared__ uint32_t s_tmem[1];
    __shared__ __align__(8) uint64_t s_mbar[1];
    __shared__ float s_d, s_r;
    int tid = threadIdx.x, wid = tid >> 5, lane = tid & 31;

    if (wid == 0) { TC_ALLOC(smem_u32(s_tmem), 128); TC_RELINQ(); }
    if (tid == 0) { MBAR_INIT(smem_u32(s_mbar), 1); s_d = 0.f; s_r = 0.f; }
    for (int idx = tid; idx < 4096; idx += 128) {
        int m = idx >> 5, k = idx & 31;
        *(float*)((char*)sma + SW128((uint32_t)(m * 128 + k * 4))) = tva(m, k);
    }
    for (int idx = tid; idx < 1024; idx += 128) {
        int n = idx >> 5, k = idx & 31;
        *(float*)((char*)smb + SW128((uint32_t)(n * 128 + k * 4))) = tvb(n, k);
    }
    __syncthreads();
    uint32_t tmem = s_tmem[0], mb = smem_u32(s_mbar);
    if (tid == 0) {
        FENCE_ASYNC();
        uint64_t ad = desc_k(smem_u32(sma)), bd = desc_k(smem_u32(smb));
#pragma unroll
        for (int ks = 0; ks < 4; ++ks)
            mma32(tmem, ad + ks * 2, bd + ks * 2, ks > 0 ? 1u : 0u);
        TC_COMMIT(mb);
    }
    __syncthreads();
    MBAR_WAIT(mb, 0);
    TC_FENCE_AFTER();

    uint32_t r[32];
    LDTM_X32(r, tmem);
    TC_WAIT_LD();
    int m = wid * 32 + lane;
    float d = 0.f, rf = 0.f;
#pragma unroll 4
    for (int n = 0; n < 32; ++n) {
        float ref = 0.f;
        for (int k = 0; k < 32; ++k) ref += tva(m, k) * tvb(n, k);
        d  += fabsf(__uint_as_float(r[n]) - ref);
        rf += fabsf(ref);
    }
    atomicAdd(&s_d, d); atomicAdd(&s_r, rf);
    __syncthreads();
    if (tid == 0) g_tc_ok = (s_d <= 0.01f * s_r + 1e-3f) ? 1 : 0;
    __syncthreads();
    if (wid == 0) TC_DEALLOC(tmem, 128);
#else
    if (threadIdx.x == 0) g_tc_ok = 0;
#endif
}

// ---------------- prep kernels ----------------
__global__ void rnd_kernel(const float4* __restrict__ src, float4* __restrict__ dst, int n4) {
    int i = blockIdx.x * blockDim.x + threadIdx.x, st = gridDim.x * blockDim.x;
    for (; i < n4; i += st) {
        float4 v = src[i];
        v.x = f2tf(v.x); v.y = f2tf(v.y); v.z = f2tf(v.z); v.w = f2tf(v.w);
        dst[i] = v;
    }
}
// W[e][K][N] -> WT[e][N][K], tf32-rounded; only if tc path live
__global__ void transpose_kernel(const float* __restrict__ src, float* __restrict__ dst,
                                 int K, int N) {
    if (g_tc_ok == 0) return;
    __shared__ float t[32][33];
    int e = blockIdx.z;
    int k0 = blockIdx.x * 32, n0 = blockIdx.y * 32;
    const float* S = src + ((size_t)e * K + k0) * N + n0;
    float* D = dst + ((size_t)e * N + n0) * K + k0;
    int tx = threadIdx.x & 31, ty = threadIdx.x >> 5;
#pragma unroll
    for (int r = 0; r < 32; r += 8)
        t[ty + r][tx] = S[(size_t)(ty + r) * N + tx];
    __syncthreads();
#pragma unroll
    for (int r = 0; r < 32; r += 8)
        D[(size_t)(ty + r) * K + tx] = f2tf(t[tx][ty + r]);
}
__global__ void init_kernel() { if (threadIdx.x < NEXP) g_counts[threadIdx.x] = 0; }

__global__ void route_kernel(const float* __restrict__ logits) {
    int t = blockIdx.x * blockDim.x + threadIdx.x;
    if (t >= TOKENS) return;
    float l[NEXP];
    const float* lp = logits + (size_t)t * NEXP;
#pragma unroll
    for (int i = 0; i < NEXP; ++i) l[i] = lp[i];
    float val[TOPK]; int sel[TOPK];
#pragma unroll
    for (int k = 0; k < TOPK; ++k) {
        float best = -1e30f; int bi = 0;
#pragma unroll
        for (int i = 0; i < NEXP; ++i)
            if (l[i] > best) { best = l[i]; bi = i; }
        val[k] = best; sel[k] = bi; l[bi] = -1e30f;
    }
    float m = val[0], s = 0.f, w[TOPK];
#pragma unroll
    for (int k = 0; k < TOPK; ++k) { w[k] = __expf(val[k] - m); s += w[k]; }
    float inv = 1.f / s;
#pragma unroll
    for (int k = 0; k < TOPK; ++k) {
        g_pair_e[t * TOPK + k] = sel[k];
        g_pair_w[t * TOPK + k] = w[k] * inv;
        atomicAdd(&g_counts[sel[k]], 1);
    }
}
__global__ void scan_kernel() {
    if (threadIdx.x == 0) {
        int acc = 0;
        for (int e = 0; e < NEXP; ++e) { g_offsets[e] = acc; g_cursor[e] = acc; acc += g_counts[e]; }
        g_offsets[NEXP] = acc;
    }
}
__global__ void scatter_kernel() {
    int p = blockIdx.x * blockDim.x + threadIdx.x;
    if (p >= NPAIRS) return;
    int slot = atomicAdd(&g_cursor[g_pair_e[p]], 1);
    g_row_token[slot]  = p >> 3;
    g_row_weight[slot] = g_pair_w[p];
    g_s2p[slot] = p;
}

// ================= tcgen05 path (all K-major) =================
__global__ void __launch_bounds__(256, 2)
gemm1_tc() {
#ifdef TC_OK
    if (g_tc_ok == 0) return;
    int e = blockIdx.z;
    int off = g_offsets[e], cnt = g_offsets[e + 1] - off;
    int m0 = blockIdx.x * 128;
    if (m0 >= cnt) return;
    int n0 = blockIdx.y * 128;

    extern __shared__ char dyn[];
    uint32_t sbase = (smem_u32(dyn) + 1023u) & ~1023u;
    __shared__ uint32_t s_tmem[1];
    __shared__ __align__(8) uint64_t s_mbar[2];
    int tid = threadIdx.x, wid = tid >> 5, lane = tid & 31;

    if (wid == 0) { TC_ALLOC(smem_u32(s_tmem), 256); TC_RELINQ(); }
    if (tid == 0) { MBAR_INIT(smem_u32(&s_mbar[0]), 1); MBAR_INIT(smem_u32(&s_mbar[1]), 1); }
    __syncthreads();
    uint32_t tmem = s_tmem[0];
    uint32_t mbar[2] = { smem_u32(&s_mbar[0]), smem_u32(&s_mbar[1]) };

    const size_t wb = (size_t)e * HIDDEN * INTER;
    int maxslot = off + cnt - 1;
    const float* asrc[4]; const float* gsrc[4]; const float* usrc[4];
    uint32_t aoff[4], boff[4];
#pragma unroll
    for (int j = 0; j < 4; ++j) {
        int id = tid + j * 256;
        int row = id >> 3, c = id & 7;
        int slot = off + m0 + row; if (slot > maxslot) slot = maxslot;
        asrc[j] = g_hid + (size_t)g_row_token[slot] * HIDDEN + c * 4;
        // B rows are inter-positions, K contiguous (transposed weights)
        gsrc[j] = g_wtg + wb + (size_t)(n0 + row) * HIDDEN + c * 4;
        usrc[j] = g_wtu + wb + (size_t)(n0 + row) * HIDDEN + c * 4;
        aoff[j] = SW128((uint32_t)(row * 128 + c * 16));
        boff[j] = aoff[j];
    }
    auto load_tile = [&](int s, int k0) {
        uint32_t sb = sbase + s * STAGE;
#pragma unroll
        for (int j = 0; j < 4; ++j) CP16(sb + aoff[j], asrc[j] + k0);
#pragma unroll
        for (int j = 0; j < 4; ++j) CP16(sb + 16384u + boff[j], gsrc[j] + k0);
#pragma unroll
        for (int j = 0; j < 4; ++j) CP16(sb + 32768u + boff[j], usrc[j] + k0);
    };

    load_tile(0, 0); CP_COMMIT;
    load_tile(1, BK); CP_COMMIT;
    for (int kt = 0; kt < KT1; ++kt) {
        int s = kt & 1;
        if (kt < KT1 - 1) CP_WAIT(1); else CP_WAIT(0);
        __syncthreads();
        if (tid == 0) {
            FENCE_ASYNC();
            uint32_t sb = sbase + s * STAGE;
            uint64_t ad = desc_k(sb);
            uint64_t bg = desc_k(sb + 16384u), bu = desc_k(sb + 32768u);
#pragma unroll
            for (int ks = 0; ks < 4; ++ks) {
                uint32_t acc = (kt > 0 || ks > 0) ? 1u : 0u;
#pragma unroll
                for (int j = 0; j < 4; ++j) {
                    mma32(tmem + j * 32,       ad + ks * 2, bg + j * 256 + ks * 2, acc);
                    mma32(tmem + 128 + j * 32, ad + ks * 2, bu + j * 256 + ks * 2, acc);
                }
            }
            TC_COMMIT(mbar[s]);
        }
        if (kt + 2 < KT1) {
            MBAR_WAIT(mbar[s], (kt >> 1) & 1);
            load_tile(s, (kt + 2) * BK); CP_COMMIT;
        }
    }
    MBAR_WAIT(mbar[1], (KT1 / 2 - 1) & 1);
    TC_FENCE_AFTER();

    int p = wid & 3, row = p * 32 + lane;
    bool valid = (m0 + row) < cnt;
    float* dst = g_act + (size_t)(off + m0 + row) * INTER + n0;
    int cb0 = (wid >> 2) * 2;
#pragma unroll
    for (int cb = 0; cb < 2; ++cb) {
        int c0 = (cb0 + cb) * 32;
        uint32_t rg[32], ru[32];
        LDTM_X32(rg, tmem + c0);
        LDTM_X32(ru, tmem + 128 + c0);
        TC_WAIT_LD();
        if (valid) {
#pragma unroll
            for (int i = 0; i < 32; i += 4) {
                float4 v;
#pragma unroll
                for (int q = 0; q < 4; ++q) {
                    float g = __uint_as_float(rg[i + q]);
                    float u = __uint_as_float(ru[i + q]);
                    ((float*)&v)[q] = f2tf(g / (1.f + __expf(-g)) * u);
                }
                *(float4*)(dst + c0 + i) = v;
            }
        }
    }
    __syncthreads();
    if (wid == 0) TC_DEALLOC(tmem, 256);
#endif
}

__global__ void __launch_bounds__(256, 2)
gemm2_tc() {
#ifdef TC_OK
    if (g_ok1 == 0) return;
    int e = blockIdx.z;
    int off = g_offsets[e], cnt = g_offsets[e + 1] - off;
    int m0 = blockIdx.x * 128;
    if (m0 >= cnt) return;
    int n0 = blockIdx.y * 256;

    extern __shared__ char dyn[];
    uint32_t sbase = (smem_u32(dyn) + 1023u) & ~1023u;
    __shared__ uint32_t s_tmem[1];
    __shared__ __align__(8) uint64_t s_mbar[2];
    int tid = threadIdx.x, wid = tid >> 5, lane = tid & 31;

    if (wid == 0) { TC_ALLOC(smem_u32(s_tmem), 256); TC_RELINQ(); }
    if (tid == 0) { MBAR_INIT(smem_u32(&s_mbar[0]), 1); MBAR_INIT(smem_u32(&s_mbar[1]), 1); }
    __syncthreads();
    uint32_t tmem = s_tmem[0];
    uint32_t mbar[2] = { smem_u32(&s_mbar[0]), smem_u32(&s_mbar[1]) };

    const size_t wb = (size_t)e * INTER * HIDDEN;
    const float* asrc[4]; uint32_t aoff[4];
    const float* bsrc[8]; uint32_t boff[8];
#pragma unroll
    for (int j = 0; j < 4; ++j) {
        int id = tid + j * 256;
        int row = id >> 3, c = id & 7;
        int ar = off + m0 + row; if (ar > NPAIRS - 1) ar = NPAIRS - 1;
        asrc[j] = g_act + (size_t)ar * INTER + c * 4;
        aoff[j] = SW128((uint32_t)(row * 128 + c * 16));
    }
#pragma unroll
    for (int j = 0; j < 8; ++j) {
        int id = tid + j * 256;
        int row = id >> 3, c = id & 7;     // row: 0..255 hidden-positions
        bsrc[j] = g_wtd + wb + (size_t)(n0 + row) * INTER + c * 4;
        boff[j] = SW128((uint32_t)(row * 128 + c * 16));
    }
    auto load_tile = [&](int s, int k0) {
        uint32_t sb = sbase + s * STAGE;
#pragma unroll
        for (int j = 0; j < 4; ++j) CP16(sb + aoff[j], asrc[j] + k0);
#pragma unroll
        for (int j = 0; j < 8; ++j) CP16(sb + 16384u + boff[j], bsrc[j] + k0);
    };

    load_tile(0, 0); CP_COMMIT;
    load_tile(1, BK); CP_COMMIT;
    for (int kt = 0; kt < KT2; ++kt) {
        int s = kt & 1;
        if (kt < KT2 - 1) CP_WAIT(1); else CP_WAIT(0);
        __syncthreads();
        if (tid == 0) {
            FENCE_ASYNC();
            uint32_t sb = sbase + s * STAGE;
            uint64_t ad = desc_k(sb);
            uint64_t bd = desc_k(sb + 16384u);
#pragma unroll
            for (int ks = 0; ks < 4; ++ks) {
                uint32_t acc = (kt > 0 || ks > 0) ? 1u : 0u;
#pragma unroll
                for (int j = 0; j < 8; ++j)
                    mma32(tmem + j * 32, ad + ks * 2, bd + j * 256 + ks * 2, acc);
            }
            TC_COMMIT(mbar[s]);
        }
        if (kt + 2 < KT2) {
            MBAR_WAIT(mbar[s], (kt >> 1) & 1);
            load_tile(s, (kt + 2) * BK); CP_COMMIT;
        }
    }
    MBAR_WAIT(mbar[1], (KT2 / 2 - 1) & 1);
    TC_FENCE_AFTER();

    int p = wid & 3, row = p * 32 + lane;
    bool valid = (m0 + row) < cnt;
    int slot = off + m0 + row; if (slot > NPAIRS - 1) slot = NPAIRS - 1;
    float w = g_row_weight[slot];
    float* dst = g_pout + (size_t)g_s2p[slot] * HIDDEN + n0;
    int chalf = (wid >> 2) * 128;
#pragma unroll
    for (int cb = 0; cb < 4; ++cb) {
        int c0 = chalf + cb * 32;
        uint32_t r[32];
        LDTM_X32(r, tmem + c0);
        TC_WAIT_LD();
        if (valid) {
#pragma unroll
            for (int i = 0; i < 32; i += 4) {
                float4 v;
                ((float*)&v)[0] = __uint_as_float(r[i])     * w;
                ((float*)&v)[1] = __uint_as_float(r[i + 1]) * w;
                ((float*)&v)[2] = __uint_as_float(r[i + 2]) * w;
                ((float*)&v)[3] = __uint_as_float(r[i + 3]) * w;
                *(float4*)(dst + c0 + i) = v;
            }
        }
    }
    __syncthreads();
    if (wid == 0) TC_DEALLOC(tmem, 256);
#endif
}

// ---------------- verifiers ----------------
__global__ void verify1_kernel() {
    if (g_tc_ok == 0) { if (threadIdx.x == 0) g_ok1 = 0; return; }
    int j = threadIdx.x * 24;                 // spans all 6 n-blocks
    int e = 0;
    while (g_offsets[e + 1] < 1) ++e;
    int tok = g_row_token[0];
    const float* h  = g_hid + (size_t)tok * HIDDEN;
    const float* wg = g_wtg + (size_t)e * HIDDEN * INTER + (size_t)j * HIDDEN;
    const float* wu = g_wtu + (size_t)e * HIDDEN * INTER + (size_t)j * HIDDEN;
    float ag = 0.f, au = 0.f;
    for (int k = 0; k < HIDDEN; ++k) { ag += h[k] * wg[k]; au += h[k] * wu[k]; }
    float ref = f2tf(ag / (1.f + expf(-ag)) * au);
    float d = fabsf(g_act[j] - ref), r = fabsf(ref);
#pragma unroll
    for (int o = 16; o; o >>= 1) {
        d += __shfl_xor_sync(~0u, d, o);
        r += __shfl_xor_sync(~0u, r, o);
    }
    if (threadIdx.x == 0) g_ok1 = (d <= 0.02f * r + 1e-2f) ? 1 : 0;
}
__global__ void verify2_kernel() {
    if (g_ok1 == 0) { if (threadIdx.x == 0) g_ok2 = 0; return; }
    int n = threadIdx.x * 64;                 // spans both n-blocks
    int e = 0;
    while (g_offsets[e + 1] < 1) ++e;
    int p = g_s2p[0];
    float w = g_row_weight[0];
    const float* a  = g_act;
    const float* wd = g_wtd + (size_t)e * INTER * HIDDEN + (size_t)n * INTER;
    float acc = 0.f;
    for (int k = 0; k < INTER; ++k) acc += a[k] * wd[k];
    float ref = acc * w;
    float d = fabsf(g_pout[(size_t)p * HIDDEN + n] - ref), r = fabsf(ref);
#pragma unroll
    for (int o = 16; o; o >>= 1) {
        d += __shfl_xor_sync(~0u, d, o);
        r += __shfl_xor_sync(~0u, r, o);
    }
    if (threadIdx.x == 0) g_ok2 = (d <= 0.02f * r + 1e-2f) ? 1 : 0;
}

// ================= legacy mma.sync path (fallback) =================
#define MMA_TF32(c, a, b)                                                     \
    asm volatile(                                                             \
        "mma.sync.aligned.m16n8k8.row.col.f32.tf32.tf32.f32 "                 \
        "{%0,%1,%2,%3},{%4,%5,%6,%7},{%8,%9},{%0,%1,%2,%3};"                  \
        : "+f"((c)[0]), "+f"((c)[1]), "+f"((c)[2]), "+f"((c)[3])              \
        : "r"((a)[0]), "r"((a)[1]), "r"((a)[2]), "r"((a)[3]),                 \
          "r"((b)[0]), "r"((b)[1]))

__global__ void __launch_bounds__(256, 2)
gemm1_legacy(const float* __restrict__ gate_w, const float* __restrict__ up_w) {
    if (g_ok1) return;
    int e = blockIdx.z;
    int off = g_offsets[e], cnt = g_offsets[e + 1] - off;
    int m0 = blockIdx.x * 128;
    if (m0 >= cnt) return;
    int n0 = blockIdx.y * 64;

    __shared__ float sA [2][128][20];
    __shared__ float sBg[2][16][68];
    __shared__ float sBu[2][16][68];

    int tid = threadIdx.x;
    const size_t wbase = (size_t)e * HIDDEN * INTER;
    int maxslot = off + cnt - 1;

    const float* asrc[2]; int arowi[2], akc[2];
#pragma unroll
    for (int j = 0; j < 2; ++j) {
        int c = tid + j * 256;
        int row = c >> 2, kc = (c & 3) << 2;
        int slot = off + m0 + row; if (slot > maxslot) slot = maxslot;
        asrc[j] = g_hid + (size_t)g_row_token[slot] * HIDDEN + kc;
        arowi[j] = row; akc[j] = kc;
    }
    int bkr = tid >> 4, bnc = (tid & 15) << 2;
    const float* gsrc = gate_w + wbase + (size_t)bkr * INTER + n0 + bnc;
    const float* usrc = up_w   + wbase + (size_t)bkr * INTER + n0 + bnc;

    auto load_tile = [&](int s, int k0) {
#pragma unroll
        for (int j = 0; j < 2; ++j)
            CP16(smem_u32(&sA[s][arowi[j]][akc[j]]), asrc[j] + k0);
        CP16(smem_u32(&sBg[s][bkr][bnc]), gsrc + (size_t)k0 * INTER);
        CP16(smem_u32(&sBu[s][bkr][bnc]), usrc + (size_t)k0 * INTER);
    };

    float cg[2][4][4] = {}, cu[2][4][4] = {};
    int warp = tid >> 5, lane = tid & 31;
    int wm = warp >> 1, wn = warp & 1;
    int gid = lane >> 2, tig = lane & 3;

    load_tile(0, 0); CP_COMMIT;
    const int KT = HIDDEN / 16;
    for (int kt = 0; kt < KT; ++kt) {
        int s = kt & 1;
        if (kt + 1 < KT) { load_tile(s ^ 1, (kt + 1) * 16); CP_COMMIT; CP_WAIT(1); }
        else             { CP_WAIT(0); }
        __syncthreads();
#pragma unroll
        for (int ks = 0; ks < 2; ++ks) {
            int k8 = ks * 8;
            uint32_t af[2][4];
#pragma unroll
            for (int mt = 0; mt < 2; ++mt) {
                int r = wm * 32 + mt * 16;
                af[mt][0] = f2tfu(sA[s][r + gid    ][k8 + tig    ]);
                af[mt][1] = f2tfu(sA[s][r + gid + 8][k8 + tig    ]);
                af[mt][2] = f2tfu(sA[s][r + gid    ][k8 + tig + 4]);
                af[mt][3] = f2tfu(sA[s][r + gid + 8][k8 + tig + 4]);
            }
            uint32_t bg[4][2], bu[4][2];
#pragma unroll
            for (int nt = 0; nt < 4; ++nt) {
                int cix = wn * 32 + nt * 8 + gid;
                bg[nt][0] = f2tfu(sBg[s][k8 + tig    ][cix]);
                bg[nt][1] = f2tfu(sBg[s][k8 + tig + 4][cix]);
                bu[nt][0] = f2tfu(sBu[s][k8 + tig    ][cix]);
                bu[nt][1] = f2tfu(sBu[s][k8 + tig + 4][cix]);
            }
#pragma unroll
            for (int mt = 0; mt < 2; ++mt)
#pragma unroll
                for (int nt = 0; nt < 4; ++nt) {
                    MMA_TF32(cg[mt][nt], af[mt], bg[nt]);
                    MMA_TF32(cu[mt][nt], af[mt], bu[nt]);
                }
        }
        __syncthreads();
    }
#pragma unroll
    for (int mt = 0; mt < 2; ++mt) {
#pragma unroll
        for (int i = 0; i < 4; ++i) {
            int row  = wm * 32 + mt * 16 + gid + ((i >> 1) << 3);
            int srow = m0 + row;
            if (srow >= cnt) continue;
            size_t base = (size_t)(off + srow) * INTER + n0 + wn * 32;
#pragma unroll
            for (int nt = 0; nt < 4; ++nt) {
                float g = cg[mt][nt][i], u = cu[mt][nt][i];
                g_act[base + nt * 8 + 2 * tig + (i & 1)] = f2tf(g / (1.f + __expf(-g)) * u);
            }
        }
    }
}

__global__ void __launch_bounds__(256, 2)
gemm2_legacy(const float* __restrict__ down_w) {
    if (g_ok2) return;
    int e = blockIdx.z;
    int off = g_offsets[e], cnt = g_offsets[e + 1] - off;
    int m0 = blockIdx.x * 128;
    if (m0 >= cnt) return;
    int n0 = blockIdx.y * 128;

    __shared__ float sA[2][128][20];
    __shared__ float sB[2][16][132];

    int tid = threadIdx.x;
    const size_t wbase = (size_t)e * INTER * HIDDEN;

    const float* asrc[2]; int arowi[2], akc[2];
#pragma unroll
    for (int j = 0; j < 2; ++j) {
        int c = tid + j * 256;
        int row = c >> 2, kc = (c & 3) << 2;
        int ar = off + m0 + row; if (ar > NPAIRS - 1) ar = NPAIRS - 1;
        asrc[j] = g_act + (size_t)ar * INTER + kc;
        arowi[j] = row; akc[j] = kc;
    }
    const float* bsrc[2]; int bkri[2], bnci[2];
#pragma unroll
    for (int j = 0; j < 2; ++j) {
        int c = tid + j * 256;
        int kr = c >> 5, nc = (c & 31) << 2;
        bsrc[j] = down_w + wbase + (size_t)kr * HIDDEN + n0 + nc;
        bkri[j] = kr; bnci[j] = nc;
    }
    auto load_tile = [&](int s, int k0) {
#pragma unroll
        for (int j = 0; j < 2; ++j)
            CP16(smem_u32(&sA[s][arowi[j]][akc[j]]), asrc[j] + k0);
#pragma unroll
        for (int j = 0; j < 2; ++j)
            CP16(smem_u32(&sB[s][bkri[j]][bnci[j]]), bsrc[j] + (size_t)k0 * HIDDEN);
    };

    float acc[2][8][4] = {};
    int warp = tid >> 5, lane = tid & 31;
    int wm = warp >> 1, wn = warp & 1;
    int gid = lane >> 2, tig = lane & 3;

    load_tile(0, 0); CP_COMMIT;
    const int KT = INTER / 16;
    for (int kt = 0; kt < KT; ++kt) {
        int s = kt & 1;
        if (kt + 1 < KT) { load_tile(s ^ 1, (kt + 1) * 16); CP_COMMIT; CP_WAIT(1); }
        else             { CP_WAIT(0); }
        __syncthreads();
#pragma unroll
        for (int ks = 0; ks < 2; ++ks) {
            int k8 = ks * 8;
            uint32_t af[2][4];
#pragma unroll
            for (int mt = 0; mt < 2; ++mt) {
                int r = wm * 32 + mt * 16;
                af[mt][0] = f2tfu(sA[s][r + gid    ][k8 + tig    ]);
                af[mt][1] = f2tfu(sA[s][r + gid + 8][k8 + tig    ]);
                af[mt][2] = f2tfu(sA[s][r + gid    ][k8 + tig + 4]);
                af[mt][3] = f2tfu(sA[s][r + gid + 8][k8 + tig + 4]);
            }
            uint32_t bf[8][2];
#pragma unroll
            for (int nt = 0; nt < 8; ++nt) {
                int cix = wn * 64 + nt * 8 + gid;
                bf[nt][0] = f2tfu(sB[s][k8 + tig    ][cix]);
                bf[nt][1] = f2tfu(sB[s][k8 + tig + 4][cix]);
            }
#pragma unroll
            for (int mt = 0; mt < 2; ++mt)
#pragma unroll
                for (int nt = 0; nt < 8; ++nt)
                    MMA_TF32(acc[mt][nt], af[mt], bf[nt]);
        }
        __syncthreads();
    }
#pragma unroll
    for (int mt = 0; mt < 2; ++mt) {
#pragma unroll
        for (int i = 0; i < 4; ++i) {
            int row  = wm * 32 + mt * 16 + gid + ((i >> 1) << 3);
            int srow = m0 + row;
            if (srow >= cnt) continue;
            int slot = off + srow;
            float w  = g_row_weight[slot];
            float* orow = g_pout + (size_t)g_s2p[slot] * HIDDEN + n0 + wn * 64;
#pragma unroll
            for (int nt = 0; nt < 8; ++nt)
                orow[nt * 8 + 2 * tig + (i & 1)] = acc[mt][nt][i] * w;
        }
    }
}

// ---------------- combine: sum 8 contiguous rows per token -----------------
__global__ void combine_kernel(float* __restrict__ out) {
    int t = blockIdx.x, c = threadIdx.x;  // 512 threads
    const float* base = g_pout + (size_t)t * TOPK * HIDDEN + c * 4;
    float4 acc = make_float4(0.f, 0.f, 0.f, 0.f);
#pragma unroll
    for (int k = 0; k < TOPK; ++k) {
        float4 v = *(const float4*)(base + (size_t)k * HIDDEN);
        acc.x += v.x; acc.y += v.y; acc.z += v.z; acc.w += v.w;
    }
    *(float4*)(out + (size_t)t * HIDDEN + c * 4) = acc;
}

// ---------------- launch ----------------
extern "C" void kernel_launch(void* const* d_in, const int* in_sizes, int n_in,
                              void* d_out, int out_size) {
    const float* hidden = (const float*)d_in[0];
    const float* logits = (const float*)d_in[1];
    const float* gate   = (const float*)d_in[2];
    const float* up     = (const float*)d_in[3];
    const float* down   = (const float*)d_in[4];
    float* out = (float*)d_out;

    cudaFuncSetAttribute(gemm1_tc, cudaFuncAttributeMaxDynamicSharedMemorySize, 2 * STAGE + 1024);
    cudaFuncSetAttribute(gemm2_tc, cudaFuncAttributeMaxDynamicSharedMemorySize, 2 * STAGE + 1024);

    float *wtg, *wtu, *wtd, *rh;
    cudaGetSymbolAddress((void**)&wtg, g_wtg);
    cudaGetSymbolAddress((void**)&wtu, g_wtu);
    cudaGetSymbolAddress((void**)&wtd, g_wtd);
    cudaGetSymbolAddress((void**)&rh,  g_hid);

    selftest_kernel <<<1, 128>>>();
    rnd_kernel      <<<2048, 512>>>((const float4*)hidden, (float4*)rh, TOKENS * HIDDEN / 4);
    transpose_kernel<<<dim3(HIDDEN / 32, INTER / 32, NEXP), 256>>>(gate, wtg, HIDDEN, INTER);
    transpose_kernel<<<dim3(HIDDEN / 32, INTER / 32, NEXP), 256>>>(up,   wtu, HIDDEN, INTER);
    transpose_kernel<<<dim3(INTER / 32, HIDDEN / 32, NEXP), 256>>>(down, wtd, INTER, HIDDEN);
    init_kernel     <<<1, 64>>>();
    route_kernel    <<<TOKENS / 256, 256>>>(logits);
    scan_kernel     <<<1, 32>>>();
    scatter_kernel  <<<NPAIRS / 256, 256>>>();
    gemm1_tc        <<<dim3(MCAP / 128, INTER / 128, NEXP), 256, 2 * STAGE + 1024>>>();
    verify1_kernel  <<<1, 32>>>();
    gemm1_legacy    <<<dim3(MCAP / 128, INTER / 64,  NEXP), 256>>>(gate, up);
    gemm2_tc        <<<dim3(MCAP / 128, HIDDEN / 256, NEXP), 256, 2 * STAGE + 1024>>>();
    verify2_kernel  <<<1, 32>>>();
    gemm2_legacy    <<<dim3(MCAP / 128, HIDDEN / 128, NEXP), 256>>>(down);
    combine_kernel  <<<TOKENS, 512>>>(out);
}

// round 6
// speedup vs baseline: 1.2913x; 1.0742x over previous
#include <cuda_runtime.h>
#include <cstdint>

#if defined(__CUDA_ARCH_FEAT_SM103_ALL) || defined(__CUDA_ARCH_FEAT_SM100_ALL) || defined(__CUDA_ARCH_FEAT_SM101_ALL)
#define TC_OK 1
#endif

#define TOKENS 4096
#define HIDDEN 2048
#define INTER  768
#define NEXP   64
#define TOPK   8
#define NPAIRS (TOKENS*TOPK)
#define MCAP   2048
#define BK     32
#define STAGE1 65536        // A 32KB + Bg 16KB + Bu 16KB
#define STAGE2 65536        // A 32KB + B 32KB
#define KT1    (HIDDEN/BK)  // 64
#define KT2    (INTER/BK)   // 24
#define WSZ    100663296    // 64*2048*768

__device__ int   g_tc_ok;
__device__ int   g_ok1;
__device__ int   g_ok2;
__device__ int   g_counts[NEXP];
__device__ int   g_offsets[NEXP+1];
__device__ int   g_cursor[NEXP];
__device__ int   g_pair_e[NPAIRS];
__device__ float g_pair_w[NPAIRS];
__device__ int   g_row_token[NPAIRS];
__device__ float g_row_weight[NPAIRS];
__device__ int   g_s2p[NPAIRS];
__device__ float g_act[(size_t)NPAIRS * INTER];
__device__ float g_pout[(size_t)NPAIRS * HIDDEN];
__device__ float g_hid[(size_t)TOKENS * HIDDEN];
__device__ float g_wtg[WSZ];   // gate^T [E][INTER][HIDDEN]
__device__ float g_wtu[WSZ];   // up^T   [E][INTER][HIDDEN]
__device__ float g_wtd[WSZ];   // down^T [E][HIDDEN][INTER]

__device__ __forceinline__ uint32_t smem_u32(const void* p) {
    return (uint32_t)__cvta_generic_to_shared(p);
}
__device__ __forceinline__ float f2tf(float x) {
    uint32_t r;
    asm("cvt.rna.tf32.f32 %0, %1;" : "=r"(r) : "f"(x));
    return __uint_as_float(r);
}
__device__ __forceinline__ uint32_t f2tfu(float x) {
    uint32_t r;
    asm("cvt.rna.tf32.f32 %0, %1;" : "=r"(r) : "f"(x));
    return r;
}
#define SW128(o) ((o) ^ (((o) >> 3) & 0x70))
#define CP16(d, s) asm volatile("cp.async.cg.shared.global [%0], [%1], 16;\n" :: "r"(d), "l"(s))
#define CP_COMMIT  asm volatile("cp.async.commit_group;\n")
#define CP_WAIT(n) asm volatile("cp.async.wait_group %0;\n" :: "n"(n))
#define MBAR_INIT(mb, c) asm volatile("mbarrier.init.shared.b64 [%0], %1;" :: "r"(mb), "r"(c) : "memory")
#define MBAR_WAIT(mb, ph)                                                     \
    asm volatile("{\n\t.reg .pred P1;\n\t"                                    \
        "WL_%=:\n\t"                                                          \
        "mbarrier.try_wait.parity.acquire.cta.shared::cta.b64 P1, [%0], %1, 0x989680;\n\t" \
        "@P1 bra.uni WD_%=;\n\t"                                              \
        "bra.uni WL_%=;\n\t"                                                  \
        "WD_%=:\n\t}" :: "r"(mb), "r"(ph) : "memory")

#ifdef TC_OK
#define TC_ALLOC(sm, n)  asm volatile("tcgen05.alloc.cta_group::1.sync.aligned.shared::cta.b32 [%0], %1;" :: "r"(sm), "r"(n) : "memory")
#define TC_DEALLOC(t, n) asm volatile("tcgen05.dealloc.cta_group::1.sync.aligned.b32 %0, %1;" :: "r"(t), "r"(n))
#define TC_RELINQ()      asm volatile("tcgen05.relinquish_alloc_permit.cta_group::1.sync.aligned;")
#define TC_COMMIT(mb)    asm volatile("tcgen05.commit.cta_group::1.mbarrier::arrive::one.shared::cluster.b64 [%0];" :: "r"(mb) : "memory")
#define TC_FENCE_AFTER() asm volatile("tcgen05.fence::after_thread_sync;" ::: "memory")
#define TC_WAIT_LD()     asm volatile("tcgen05.wait::ld.sync.aligned;" ::: "memory")
#define FENCE_ASYNC()    asm volatile("fence.proxy.async.shared::cta;" ::: "memory")
#define LDTM_X32(r, a)                                                        \
    asm volatile("tcgen05.ld.sync.aligned.32x32b.x32.b32 "                    \
        "{%0,%1,%2,%3,%4,%5,%6,%7,%8,%9,%10,%11,%12,%13,%14,%15,"             \
        "%16,%17,%18,%19,%20,%21,%22,%23,%24,%25,%26,%27,%28,%29,%30,%31},[%32];" \
        : "=r"((r)[0]),"=r"((r)[1]),"=r"((r)[2]),"=r"((r)[3]),                \
          "=r"((r)[4]),"=r"((r)[5]),"=r"((r)[6]),"=r"((r)[7]),                \
          "=r"((r)[8]),"=r"((r)[9]),"=r"((r)[10]),"=r"((r)[11]),              \
          "=r"((r)[12]),"=r"((r)[13]),"=r"((r)[14]),"=r"((r)[15]),            \
          "=r"((r)[16]),"=r"((r)[17]),"=r"((r)[18]),"=r"((r)[19]),            \
          "=r"((r)[20]),"=r"((r)[21]),"=r"((r)[22]),"=r"((r)[23]),            \
          "=r"((r)[24]),"=r"((r)[25]),"=r"((r)[26]),"=r"((r)[27]),            \
          "=r"((r)[28]),"=r"((r)[29]),"=r"((r)[30]),"=r"((r)[31]) : "r"(a))

__device__ __forceinline__ uint64_t desc_k(uint32_t a) {   // K-major SW128
    return (uint64_t(2) << 61) | (uint64_t(1) << 46) | (uint64_t(64) << 32) |
           (uint64_t(1) << 16) | ((uint64_t)(a >> 4) & 0x3FFF);
}
// d=f32, a=b=tf32, K-major, M=128
#define IDESC32 ((1u<<4)|(2u<<7)|(2u<<10)|(4u<<17)|(8u<<24))   // N=32 (selftest)
#define IDESC64 ((1u<<4)|(2u<<7)|(2u<<10)|(8u<<17)|(8u<<24))   // N=64 (gemms)
__device__ __forceinline__ void mma_n32(uint32_t d, uint64_t ad, uint64_t bd, uint32_t acc) {
    asm volatile(
        "{\n\t.reg .pred p;\n\tsetp.ne.u32 p, %4, 0;\n\t"
        "tcgen05.mma.cta_group::1.kind::tf32 [%0], %1, %2, %3, {%5,%5,%5,%5}, p;\n\t}"
        :: "r"(d), "l"(ad), "l"(bd), "r"(IDESC32), "r"(acc), "r"(0u) : "memory");
}
__device__ __forceinline__ void mma_n64(uint32_t d, uint64_t ad, uint64_t bd, uint32_t acc) {
    asm volatile(
        "{\n\t.reg .pred p;\n\tsetp.ne.u32 p, %4, 0;\n\t"
        "tcgen05.mma.cta_group::1.kind::tf32 [%0], %1, %2, %3, {%5,%5,%5,%5}, p;\n\t}"
        :: "r"(d), "l"(ad), "l"(bd), "r"(IDESC64), "r"(acc), "r"(0u) : "memory");
}
#endif

// ---------------- self-test ----------------
__device__ __forceinline__ float tva(int m, int k) {
    return f2tf(0.01f * (float)((m * 7 + k * 13) % 31 - 15));
}
__device__ __forceinline__ float tvb(int n, int k) {
    return f2tf(0.02f * (float)((n * 5 + k * 3) % 29 - 14));
}
__global__ void selftest_kernel() {
#ifdef TC_OK
    __shared__ __align__(1024) float sma[4096];
    __shared__ __align__(1024) float smb[1024];
    __shared__ uint32_t s_tmem[1];
    __shared__ __align__(8) uint64_t s_mbar[1];
    __shared__ float s_d, s_r;
    int tid = threadIdx.x, wid = tid >> 5, lane = tid & 31;

    if (wid == 0) { TC_ALLOC(smem_u32(s_tmem), 128); TC_RELINQ(); }
    if (tid == 0) { MBAR_INIT(smem_u32(s_mbar), 1); s_d = 0.f; s_r = 0.f; }
    for (int idx = tid; idx < 4096; idx += 128) {
        int m = idx >> 5, k = idx & 31;
        *(float*)((char*)sma + SW128((uint32_t)(m * 128 + k * 4))) = tva(m, k);
    }
    for (int idx = tid; idx < 1024; idx += 128) {
        int n = idx >> 5, k = idx & 31;
        *(float*)((char*)smb + SW128((uint32_t)(n * 128 + k * 4))) = tvb(n, k);
    }
    __syncthreads();
    uint32_t tmem = s_tmem[0], mb = smem_u32(s_mbar);
    if (tid == 0) {
        FENCE_ASYNC();
        uint64_t ad = desc_k(smem_u32(sma)), bd = desc_k(smem_u32(smb));
#pragma unroll
        for (int ks = 0; ks < 4; ++ks)
            mma_n32(tmem, ad + ks * 2, bd + ks * 2, ks > 0 ? 1u : 0u);
        TC_COMMIT(mb);
    }
    __syncthreads();
    MBAR_WAIT(mb, 0);
    TC_FENCE_AFTER();

    uint32_t r[32];
    LDTM_X32(r, tmem);
    TC_WAIT_LD();
    int m = wid * 32 + lane;
    float d = 0.f, rf = 0.f;
#pragma unroll 4
    for (int n = 0; n < 32; ++n) {
        float ref = 0.f;
        for (int k = 0; k < 32; ++k) ref += tva(m, k) * tvb(n, k);
        d  += fabsf(__uint_as_float(r[n]) - ref);
        rf += fabsf(ref);
    }
    atomicAdd(&s_d, d); atomicAdd(&s_r, rf);
    __syncthreads();
    if (tid == 0) g_tc_ok = (s_d <= 0.01f * s_r + 1e-3f) ? 1 : 0;
    __syncthreads();
    if (wid == 0) TC_DEALLOC(tmem, 128);
#else
    if (threadIdx.x == 0) g_tc_ok = 0;
#endif
}

// ---------------- prep ----------------
__global__ void rnd_kernel(const float4* __restrict__ src, float4* __restrict__ dst, int n4) {
    int i = blockIdx.x * blockDim.x + threadIdx.x, st = gridDim.x * blockDim.x;
    for (; i < n4; i += st) {
        float4 v = src[i];
        v.x = f2tf(v.x); v.y = f2tf(v.y); v.z = f2tf(v.z); v.w = f2tf(v.w);
        dst[i] = v;
    }
}
// W[e][K][N] -> WT[e][N][K], tf32-rounded, float4 both directions
__global__ void transpose_kernel(const float* __restrict__ src, float* __restrict__ dst,
                                 int K, int N) {
    if (g_tc_ok == 0) return;
    __shared__ float t[32][33];
    int e = blockIdx.z;
    int k0 = blockIdx.x * 32, n0 = blockIdx.y * 32;
    int r = threadIdx.x >> 3, c4 = (threadIdx.x & 7) << 2;
    float4 v = *(const float4*)(src + ((size_t)e * K + k0 + r) * N + n0 + c4);
    t[r][c4] = v.x; t[r][c4 + 1] = v.y; t[r][c4 + 2] = v.z; t[r][c4 + 3] = v.w;
    __syncthreads();
    float4 o;
    o.x = f2tf(t[c4    ][r]);
    o.y = f2tf(t[c4 + 1][r]);
    o.z = f2tf(t[c4 + 2][r]);
    o.w = f2tf(t[c4 + 3][r]);
    *(float4*)(dst + ((size_t)e * N + n0 + r) * K + k0 + c4) = o;
}
__global__ void init_kernel() { if (threadIdx.x < NEXP) g_counts[threadIdx.x] = 0; }

__global__ void route_kernel(const float* __restrict__ logits) {
    int t = blockIdx.x * blockDim.x + threadIdx.x;
    if (t >= TOKENS) return;
    float l[NEXP];
    const float* lp = logits + (size_t)t * NEXP;
#pragma unroll
    for (int i = 0; i < NEXP; ++i) l[i] = lp[i];
    float val[TOPK]; int sel[TOPK];
#pragma unroll
    for (int k = 0; k < TOPK; ++k) {
        float best = -1e30f; int bi = 0;
#pragma unroll
        for (int i = 0; i < NEXP; ++i)
            if (l[i] > best) { best = l[i]; bi = i; }
        val[k] = best; sel[k] = bi; l[bi] = -1e30f;
    }
    float m = val[0], s = 0.f, w[TOPK];
#pragma unroll
    for (int k = 0; k < TOPK; ++k) { w[k] = __expf(val[k] - m); s += w[k]; }
    float inv = 1.f / s;
#pragma unroll
    for (int k = 0; k < TOPK; ++k) {
        g_pair_e[t * TOPK + k] = sel[k];
        g_pair_w[t * TOPK + k] = w[k] * inv;
        atomicAdd(&g_counts[sel[k]], 1);
    }
}
__global__ void scan_kernel() {
    if (threadIdx.x == 0) {
        int acc = 0;
        for (int e = 0; e < NEXP; ++e) { g_offsets[e] = acc; g_cursor[e] = acc; acc += g_counts[e]; }
        g_offsets[NEXP] = acc;
    }
}
__global__ void scatter_kernel() {
    int p = blockIdx.x * blockDim.x + threadIdx.x;
    if (p >= NPAIRS) return;
    int slot = atomicAdd(&g_cursor[g_pair_e[p]], 1);
    g_row_token[slot]  = p >> 3;
    g_row_weight[slot] = g_pair_w[p];
    g_s2p[slot] = p;
}

// ================= tcgen05 GEMM1: M=256, N=128 (gate+up) =================
__global__ void __launch_bounds__(256, 1)
gemm1_tc() {
#ifdef TC_OK
    if (g_tc_ok == 0) return;
    int e = blockIdx.z;
    int off = g_offsets[e], cnt = g_offsets[e + 1] - off;
    int m0 = blockIdx.x * 256;
    if (m0 >= cnt) return;
    int n0 = blockIdx.y * 128;

    extern __shared__ char dyn[];
    uint32_t sbase = (smem_u32(dyn) + 1023u) & ~1023u;
    __shared__ uint32_t s_tmem[1];
    __shared__ __align__(8) uint64_t s_mbar[2];
    int tid = threadIdx.x, wid = tid >> 5, lane = tid & 31;

    if (wid == 0) { TC_ALLOC(smem_u32(s_tmem), 512); TC_RELINQ(); }
    if (tid == 0) { MBAR_INIT(smem_u32(&s_mbar[0]), 1); MBAR_INIT(smem_u32(&s_mbar[1]), 1); }
    __syncthreads();
    uint32_t tmem = s_tmem[0];
    uint32_t mbar[2] = { smem_u32(&s_mbar[0]), smem_u32(&s_mbar[1]) };

    const size_t wb = (size_t)e * HIDDEN * INTER;
    int maxslot = off + cnt - 1;
    // A: 256 rows -> 2048 chunks -> 8/thread; Bg,Bu: 128 rows -> 4/thread each
    const float* asrc[8]; uint32_t aoff[8];
    const float* gsrc[4]; const float* usrc[4]; uint32_t boff[4];
#pragma unroll
    for (int j = 0; j < 8; ++j) {
        int id = tid + j * 256;
        int row = id >> 3, c = id & 7;
        int slot = off + m0 + row; if (slot > maxslot) slot = maxslot;
        asrc[j] = g_hid + (size_t)g_row_token[slot] * HIDDEN + c * 4;
        aoff[j] = SW128((uint32_t)(row * 128 + c * 16));
    }
#pragma unroll
    for (int j = 0; j < 4; ++j) {
        int id = tid + j * 256;
        int nrow = id >> 3, c = id & 7;
        gsrc[j] = g_wtg + wb + (size_t)(n0 + nrow) * HIDDEN + c * 4;
        usrc[j] = g_wtu + wb + (size_t)(n0 + nrow) * HIDDEN + c * 4;
        boff[j] = SW128((uint32_t)(nrow * 128 + c * 16));
    }
    auto load_tile = [&](int s, int k0) {
        uint32_t sb = sbase + s * STAGE1;
#pragma unroll
        for (int j = 0; j < 8; ++j) CP16(sb + aoff[j], asrc[j] + k0);
#pragma unroll
        for (int j = 0; j < 4; ++j) CP16(sb + 32768u + boff[j], gsrc[j] + k0);
#pragma unroll
        for (int j = 0; j < 4; ++j) CP16(sb + 49152u + boff[j], usrc[j] + k0);
    };

    load_tile(0, 0); CP_COMMIT;
    load_tile(1, BK); CP_COMMIT;
    for (int kt = 0; kt < KT1; ++kt) {
        int s = kt & 1;
        if (kt < KT1 - 1) CP_WAIT(1); else CP_WAIT(0);
        __syncthreads();
        if (tid == 0) {
            FENCE_ASYNC();
            uint32_t sb = sbase + s * STAGE1;
            uint64_t ad = desc_k(sb);
            uint64_t bg = desc_k(sb + 32768u), bu = desc_k(sb + 49152u);
#pragma unroll
            for (int ks = 0; ks < 4; ++ks) {
                uint32_t acc = (kt > 0 || ks > 0) ? 1u : 0u;
#pragma unroll
                for (int mh = 0; mh < 2; ++mh) {
                    uint64_t am = ad + mh * 1024 + ks * 2;   // m-half A: +16KB
#pragma unroll
                    for (int j = 0; j < 2; ++j) {
                        mma_n64(tmem + mh * 256 + j * 64,       am, bg + j * 512 + ks * 2, acc);
                        mma_n64(tmem + mh * 256 + 128 + j * 64, am, bu + j * 512 + ks * 2, acc);
                    }
                }
            }
            TC_COMMIT(mbar[s]);
        }
        if (kt + 2 < KT1) {
            MBAR_WAIT(mbar[s], (kt >> 1) & 1);
            load_tile(s, (kt + 2) * BK); CP_COMMIT;
        }
    }
    MBAR_WAIT(mbar[1], (KT1 / 2 - 1) & 1);
    TC_FENCE_AFTER();

    // epilogue: warp w -> m-half w>>2, subpartition w&3
    int mh = wid >> 2, sp = wid & 3;
    int row = mh * 128 + sp * 32 + lane;
    bool valid = (m0 + row) < cnt;
    float* dst = g_act + (size_t)(off + m0 + row) * INTER + n0;
    uint32_t tb = tmem + mh * 256;
#pragma unroll
    for (int cb = 0; cb < 4; ++cb) {
        int c0 = cb * 32;
        uint32_t rg[32], ru[32];
        LDTM_X32(rg, tb + c0);
        LDTM_X32(ru, tb + 128 + c0);
        TC_WAIT_LD();
        if (valid) {
#pragma unroll
            for (int i = 0; i < 32; i += 4) {
                float4 v;
#pragma unroll
                for (int q = 0; q < 4; ++q) {
                    float g = __uint_as_float(rg[i + q]);
                    float u = __uint_as_float(ru[i + q]);
                    ((float*)&v)[q] = f2tf(g / (1.f + __expf(-g)) * u);
                }
                *(float4*)(dst + c0 + i) = v;
            }
        }
    }
    __syncthreads();
    if (wid == 0) TC_DEALLOC(tmem, 512);
#endif
}

// ================= tcgen05 GEMM2: M=256, N=256 =================
__global__ void __launch_bounds__(256, 1)
gemm2_tc() {
#ifdef TC_OK
    if (g_ok1 == 0) return;
    int e = blockIdx.z;
    int off = g_offsets[e], cnt = g_offsets[e + 1] - off;
    int m0 = blockIdx.x * 256;
    if (m0 >= cnt) return;
    int n0 = blockIdx.y * 256;

    extern __shared__ char dyn[];
    uint32_t sbase = (smem_u32(dyn) + 1023u) & ~1023u;
    __shared__ uint32_t s_tmem[1];
    __shared__ __align__(8) uint64_t s_mbar[2];
    int tid = threadIdx.x, wid = tid >> 5, lane = tid & 31;

    if (wid == 0) { TC_ALLOC(smem_u32(s_tmem), 512); TC_RELINQ(); }
    if (tid == 0) { MBAR_INIT(smem_u32(&s_mbar[0]), 1); MBAR_INIT(smem_u32(&s_mbar[1]), 1); }
    __syncthreads();
    uint32_t tmem = s_tmem[0];
    uint32_t mbar[2] = { smem_u32(&s_mbar[0]), smem_u32(&s_mbar[1]) };

    const size_t wb = (size_t)e * INTER * HIDDEN;
    const float* asrc[8]; uint32_t aoff[8];
    const float* bsrc[8]; uint32_t boff[8];
#pragma unroll
    for (int j = 0; j < 8; ++j) {
        int id = tid + j * 256;
        int row = id >> 3, c = id & 7;
        int ar = off + m0 + row; if (ar > NPAIRS - 1) ar = NPAIRS - 1;
        asrc[j] = g_act + (size_t)ar * INTER + c * 4;
        aoff[j] = SW128((uint32_t)(row * 128 + c * 16));
        bsrc[j] = g_wtd + wb + (size_t)(n0 + row) * INTER + c * 4;
        boff[j] = aoff[j];
    }
    auto load_tile = [&](int s, int k0) {
        uint32_t sb = sbase + s * STAGE2;
#pragma unroll
        for (int j = 0; j < 8; ++j) CP16(sb + aoff[j], asrc[j] + k0);
#pragma unroll
        for (int j = 0; j < 8; ++j) CP16(sb + 32768u + boff[j], bsrc[j] + k0);
    };

    load_tile(0, 0); CP_COMMIT;
    load_tile(1, BK); CP_COMMIT;
    for (int kt = 0; kt < KT2; ++kt) {
        int s = kt & 1;
        if (kt < KT2 - 1) CP_WAIT(1); else CP_WAIT(0);
        __syncthreads();
        if (tid == 0) {
            FENCE_ASYNC();
            uint32_t sb = sbase + s * STAGE2;
            uint64_t ad = desc_k(sb);
            uint64_t bd = desc_k(sb + 32768u);
#pragma unroll
            for (int ks = 0; ks < 4; ++ks) {
                uint32_t acc = (kt > 0 || ks > 0) ? 1u : 0u;
#pragma unroll
                for (int mh = 0; mh < 2; ++mh) {
                    uint64_t am = ad + mh * 1024 + ks * 2;
#pragma unroll
                    for (int j = 0; j < 4; ++j)
                        mma_n64(tmem + mh * 256 + j * 64, am, bd + j * 512 + ks * 2, acc);
                }
            }
            TC_COMMIT(mbar[s]);
        }
        if (kt + 2 < KT2) {
            MBAR_WAIT(mbar[s], (kt >> 1) & 1);
            load_tile(s, (kt + 2) * BK); CP_COMMIT;
        }
    }
    MBAR_WAIT(mbar[1], (KT2 / 2 - 1) & 1);
    TC_FENCE_AFTER();

    int mh = wid >> 2, sp = wid & 3;
    int row = mh * 128 + sp * 32 + lane;
    bool valid = (m0 + row) < cnt;
    int slot = off + m0 + row; if (slot > NPAIRS - 1) slot = NPAIRS - 1;
    float w = g_row_weight[slot];
    float* dst = g_pout + (size_t)g_s2p[slot] * HIDDEN + n0;
    uint32_t tb = tmem + mh * 256;
#pragma unroll
    for (int cb = 0; cb < 8; ++cb) {
        int c0 = cb * 32;
        uint32_t r[32];
        LDTM_X32(r, tb + c0);
        TC_WAIT_LD();
        if (valid) {
#pragma unroll
            for (int i = 0; i < 32; i += 4) {
                float4 v;
                ((float*)&v)[0] = __uint_as_float(r[i])     * w;
                ((float*)&v)[1] = __uint_as_float(r[i + 1]) * w;
                ((float*)&v)[2] = __uint_as_float(r[i + 2]) * w;
                ((float*)&v)[3] = __uint_as_float(r[i + 3]) * w;
                *(float4*)(dst + c0 + i) = v;
            }
        }
    }
    __syncthreads();
    if (wid == 0) TC_DEALLOC(tmem, 512);
#endif
}

// ---------------- verifiers ----------------
__global__ void verify1_kernel() {
    if (g_tc_ok == 0) { if (threadIdx.x == 0) g_ok1 = 0; return; }
    int j = threadIdx.x * 24;
    int e = 0;
    while (g_offsets[e + 1] < 1) ++e;
    int tok = g_row_token[0];
    const float* h  = g_hid + (size_t)tok * HIDDEN;
    const float* wg = g_wtg + (size_t)e * HIDDEN * INTER + (size_t)j * HIDDEN;
    const float* wu = g_wtu + (size_t)e * HIDDEN * INTER + (size_t)j * HIDDEN;
    float ag = 0.f, au = 0.f;
    for (int k = 0; k < HIDDEN; ++k) { ag += h[k] * wg[k]; au += h[k] * wu[k]; }
    float ref = f2tf(ag / (1.f + expf(-ag)) * au);
    float d = fabsf(g_act[j] - ref), r = fabsf(ref);
#pragma unroll
    for (int o = 16; o; o >>= 1) {
        d += __shfl_xor_sync(~0u, d, o);
        r += __shfl_xor_sync(~0u, r, o);
    }
    if (threadIdx.x == 0) g_ok1 = (d <= 0.02f * r + 1e-2f) ? 1 : 0;
}
__global__ void verify2_kernel() {
    if (g_ok1 == 0) { if (threadIdx.x == 0) g_ok2 = 0; return; }
    int n = threadIdx.x * 64;
    int e = 0;
    while (g_offsets[e + 1] < 1) ++e;
    int p = g_s2p[0];
    float w = g_row_weight[0];
    const float* a  = g_act;
    const float* wd = g_wtd + (size_t)e * INTER * HIDDEN + (size_t)n * INTER;
    float acc = 0.f;
    for (int k = 0; k < INTER; ++k) acc += a[k] * wd[k];
    float ref = acc * w;
    float d = fabsf(g_pout[(size_t)p * HIDDEN + n] - ref), r = fabsf(ref);
#pragma unroll
    for (int o = 16; o; o >>= 1) {
        d += __shfl_xor_sync(~0u, d, o);
        r += __shfl_xor_sync(~0u, r, o);
    }
    if (threadIdx.x == 0) g_ok2 = (d <= 0.02f * r + 1e-2f) ? 1 : 0;
}

// ================= legacy mma.sync fallback =================
#define MMA_TF32(c, a, b)                                                     \
    asm volatile(                                                             \
        "mma.sync.aligned.m16n8k8.row.col.f32.tf32.tf32.f32 "                 \
        "{%0,%1,%2,%3},{%4,%5,%6,%7},{%8,%9},{%0,%1,%2,%3};"                  \
        : "+f"((c)[0]), "+f"((c)[1]), "+f"((c)[2]), "+f"((c)[3])              \
        : "r"((a)[0]), "r"((a)[1]), "r"((a)[2]), "r"((a)[3]),                 \
          "r"((b)[0]), "r"((b)[1]))

__global__ void __launch_bounds__(256, 2)
gemm1_legacy(const float* __restrict__ gate_w, const float* __restrict__ up_w) {
    if (g_ok1) return;
    int e = blockIdx.z;
    int off = g_offsets[e], cnt = g_offsets[e + 1] - off;
    int m0 = blockIdx.x * 128;
    if (m0 >= cnt) return;
    int n0 = blockIdx.y * 64;

    __shared__ float sA [2][128][20];
    __shared__ float sBg[2][16][68];
    __shared__ float sBu[2][16][68];

    int tid = threadIdx.x;
    const size_t wbase = (size_t)e * HIDDEN * INTER;
    int maxslot = off + cnt - 1;

    const float* asrc[2]; int arowi[2], akc[2];
#pragma unroll
    for (int j = 0; j < 2; ++j) {
        int c = tid + j * 256;
        int row = c >> 2, kc = (c & 3) << 2;
        int slot = off + m0 + row; if (slot > maxslot) slot = maxslot;
        asrc[j] = g_hid + (size_t)g_row_token[slot] * HIDDEN + kc;
        arowi[j] = row; akc[j] = kc;
    }
    int bkr = tid >> 4, bnc = (tid & 15) << 2;
    const float* gsrc = gate_w + wbase + (size_t)bkr * INTER + n0 + bnc;
    const float* usrc = up_w   + wbase + (size_t)bkr * INTER + n0 + bnc;

    auto load_tile = [&](int s, int k0) {
#pragma unroll
        for (int j = 0; j < 2; ++j)
            CP16(smem_u32(&sA[s][arowi[j]][akc[j]]), asrc[j] + k0);
        CP16(smem_u32(&sBg[s][bkr][bnc]), gsrc + (size_t)k0 * INTER);
        CP16(smem_u32(&sBu[s][bkr][bnc]), usrc + (size_t)k0 * INTER);
    };

    float cg[2][4][4] = {}, cu[2][4][4] = {};
    int warp = tid >> 5, lane = tid & 31;
    int wm = warp >> 1, wn = warp & 1;
    int gid = lane >> 2, tig = lane & 3;

    load_tile(0, 0); CP_COMMIT;
    const int KT = HIDDEN / 16;
    for (int kt = 0; kt < KT; ++kt) {
        int s = kt & 1;
        if (kt + 1 < KT) { load_tile(s ^ 1, (kt + 1) * 16); CP_COMMIT; CP_WAIT(1); }
        else             { CP_WAIT(0); }
        __syncthreads();
#pragma unroll
        for (int ks = 0; ks < 2; ++ks) {
            int k8 = ks * 8;
            uint32_t af[2][4];
#pragma unroll
            for (int mt = 0; mt < 2; ++mt) {
                int r = wm * 32 + mt * 16;
                af[mt][0] = f2tfu(sA[s][r + gid    ][k8 + tig    ]);
                af[mt][1] = f2tfu(sA[s][r + gid + 8][k8 + tig    ]);
                af[mt][2] = f2tfu(sA[s][r + gid    ][k8 + tig + 4]);
                af[mt][3] = f2tfu(sA[s][r + gid + 8][k8 + tig + 4]);
            }
            uint32_t bg[4][2], bu[4][2];
#pragma unroll
            for (int nt = 0; nt < 4; ++nt) {
                int cix = wn * 32 + nt * 8 + gid;
                bg[nt][0] = f2tfu(sBg[s][k8 + tig    ][cix]);
                bg[nt][1] = f2tfu(sBg[s][k8 + tig + 4][cix]);
                bu[nt][0] = f2tfu(sBu[s][k8 + tig    ][cix]);
                bu[nt][1] = f2tfu(sBu[s][k8 + tig + 4][cix]);
            }
#pragma unroll
            for (int mt = 0; mt < 2; ++mt)
#pragma unroll
                for (int nt = 0; nt < 4; ++nt) {
                    MMA_TF32(cg[mt][nt], af[mt], bg[nt]);
                    MMA_TF32(cu[mt][nt], af[mt], bu[nt]);
                }
        }
        __syncthreads();
    }
#pragma unroll
    for (int mt = 0; mt < 2; ++mt) {
#pragma unroll
        for (int i = 0; i < 4; ++i) {
            int row  = wm * 32 + mt * 16 + gid + ((i >> 1) << 3);
            int srow = m0 + row;
            if (srow >= cnt) continue;
            size_t base = (size_t)(off + srow) * INTER + n0 + wn * 32;
#pragma unroll
            for (int nt = 0; nt < 4; ++nt) {
                float g = cg[mt][nt][i], u = cu[mt][nt][i];
                g_act[base + nt * 8 + 2 * tig + (i & 1)] = f2tf(g / (1.f + __expf(-g)) * u);
            }
        }
    }
}

__global__ void __launch_bounds__(256, 2)
gemm2_legacy(const float* __restrict__ down_w) {
    if (g_ok2) return;
    int e = blockIdx.z;
    int off = g_offsets[e], cnt = g_offsets[e + 1] - off;
    int m0 = blockIdx.x * 128;
    if (m0 >= cnt) return;
    int n0 = blockIdx.y * 128;

    __shared__ float sA[2][128][20];
    __shared__ float sB[2][16][132];

    int tid = threadIdx.x;
    const size_t wbase = (size_t)e * INTER * HIDDEN;

    const float* asrc[2]; int arowi[2], akc[2];
#pragma unroll
    for (int j = 0; j < 2; ++j) {
        int c = tid + j * 256;
        int row = c >> 2, kc = (c & 3) << 2;
        int ar = off + m0 + row; if (ar > NPAIRS - 1) ar = NPAIRS - 1;
        asrc[j] = g_act + (size_t)ar * INTER + kc;
        arowi[j] = row; akc[j] = kc;
    }
    const float* bsrc[2]; int bkri[2], bnci[2];
#pragma unroll
    for (int j = 0; j < 2; ++j) {
        int c = tid + j * 256;
        int kr = c >> 5, nc = (c & 31) << 2;
        bsrc[j] = down_w + wbase + (size_t)kr * HIDDEN + n0 + nc;
        bkri[j] = kr; bnci[j] = nc;
    }
    auto load_tile = [&](int s, int k0) {
#pragma unroll
        for (int j = 0; j < 2; ++j)
            CP16(smem_u32(&sA[s][arowi[j]][akc[j]]), asrc[j] + k0);
#pragma unroll
        for (int j = 0; j < 2; ++j)
            CP16(smem_u32(&sB[s][bkri[j]][bnci[j]]), bsrc[j] + (size_t)k0 * HIDDEN);
    };

    float acc[2][8][4] = {};
    int warp = tid >> 5, lane = tid & 31;
    int wm = warp >> 1, wn = warp & 1;
    int gid = lane >> 2, tig = lane & 3;

    load_tile(0, 0); CP_COMMIT;
    const int KT = INTER / 16;
    for (int kt = 0; kt < KT; ++kt) {
        int s = kt & 1;
        if (kt + 1 < KT) { load_tile(s ^ 1, (kt + 1) * 16); CP_COMMIT; CP_WAIT(1); }
        else             { CP_WAIT(0); }
        __syncthreads();
#pragma unroll
        for (int ks = 0; ks < 2; ++ks) {
            int k8 = ks * 8;
            uint32_t af[2][4];
#pragma unroll
            for (int mt = 0; mt < 2; ++mt) {
                int r = wm * 32 + mt * 16;
                af[mt][0] = f2tfu(sA[s][r + gid    ][k8 + tig    ]);
                af[mt][1] = f2tfu(sA[s][r + gid + 8][k8 + tig    ]);
                af[mt][2] = f2tfu(sA[s][r + gid    ][k8 + tig + 4]);
                af[mt][3] = f2tfu(sA[s][r + gid + 8][k8 + tig + 4]);
            }
            uint32_t bf[8][2];
#pragma unroll
            for (int nt = 0; nt < 8; ++nt) {
                int cix = wn * 64 + nt * 8 + gid;
                bf[nt][0] = f2tfu(sB[s][k8 + tig    ][cix]);
                bf[nt][1] = f2tfu(sB[s][k8 + tig + 4][cix]);
            }
#pragma unroll
            for (int mt = 0; mt < 2; ++mt)
#pragma unroll
                for (int nt = 0; nt < 8; ++nt)
                    MMA_TF32(acc[mt][nt], af[mt], bf[nt]);
        }
        __syncthreads();
    }
#pragma unroll
    for (int mt = 0; mt < 2; ++mt) {
#pragma unroll
        for (int i = 0; i < 4; ++i) {
            int row  = wm * 32 + mt * 16 + gid + ((i >> 1) << 3);
            int srow = m0 + row;
            if (srow >= cnt) continue;
            int slot = off + srow;
            float w  = g_row_weight[slot];
            float* orow = g_pout + (size_t)g_s2p[slot] * HIDDEN + n0 + wn * 64;
#pragma unroll
            for (int nt = 0; nt < 8; ++nt)
                orow[nt * 8 + 2 * tig + (i & 1)] = acc[mt][nt][i] * w;
        }
    }
}

// ---------------- combine ----------------
__global__ void combine_kernel(float* __restrict__ out) {
    int t = blockIdx.x, c = threadIdx.x;
    const float* base = g_pout + (size_t)t * TOPK * HIDDEN + c * 4;
    float4 acc = make_float4(0.f, 0.f, 0.f, 0.f);
#pragma unroll
    for (int k = 0; k < TOPK; ++k) {
        float4 v = *(const float4*)(base + (size_t)k * HIDDEN);
        acc.x += v.x; acc.y += v.y; acc.z += v.z; acc.w += v.w;
    }
    *(float4*)(out + (size_t)t * HIDDEN + c * 4) = acc;
}

// ---------------- launch ----------------
extern "C" void kernel_launch(void* const* d_in, const int* in_sizes, int n_in,
                              void* d_out, int out_size) {
    const float* hidden = (const float*)d_in[0];
    const float* logits = (const float*)d_in[1];
    const float* gate   = (const float*)d_in[2];
    const float* up     = (const float*)d_in[3];
    const float* down   = (const float*)d_in[4];
    float* out = (float*)d_out;

    cudaFuncSetAttribute(gemm1_tc, cudaFuncAttributeMaxDynamicSharedMemorySize, 2 * STAGE1 + 1024);
    cudaFuncSetAttribute(gemm2_tc, cudaFuncAttributeMaxDynamicSharedMemorySize, 2 * STAGE2 + 1024);

    float *wtg, *wtu, *wtd, *rh;
    cudaGetSymbolAddress((void**)&wtg, g_wtg);
    cudaGetSymbolAddress((void**)&wtu, g_wtu);
    cudaGetSymbolAddress((void**)&wtd, g_wtd);
    cudaGetSymbolAddress((void**)&rh,  g_hid);

    selftest_kernel <<<1, 128>>>();
    rnd_kernel      <<<2048, 512>>>((const float4*)hidden, (float4*)rh, TOKENS * HIDDEN / 4);
    transpose_kernel<<<dim3(HIDDEN / 32, INTER / 32, NEXP), 256>>>(gate, wtg, HIDDEN, INTER);
    transpose_kernel<<<dim3(HIDDEN / 32, INTER / 32, NEXP), 256>>>(up,   wtu, HIDDEN, INTER);
    transpose_kernel<<<dim3(INTER / 32, HIDDEN / 32, NEXP), 256>>>(down, wtd, INTER, HIDDEN);
    init_kernel     <<<1, 64>>>();
    route_kernel    <<<TOKENS / 256, 256>>>(logits);
    scan_kernel     <<<1, 32>>>();
    scatter_kernel  <<<NPAIRS / 256, 256>>>();
    gemm1_tc        <<<dim3(MCAP / 256, INTER / 128, NEXP), 256, 2 * STAGE1 + 1024>>>();
    verify1_kernel  <<<1, 32>>>();
    gemm1_legacy    <<<dim3(MCAP / 128, INTER / 64,  NEXP), 256>>>(gate, up);
    gemm2_tc        <<<dim3(MCAP / 256, HIDDEN / 256, NEXP), 256, 2 * STAGE2 + 1024>>>();
    verify2_kernel  <<<1, 32>>>();
    gemm2_legacy    <<<dim3(MCAP / 128, HIDDEN / 128, NEXP), 256>>>(down);
    combine_kernel  <<<TOKENS, 512>>>(out);
}

// round 7
// speedup vs baseline: 1.3028x; 1.0089x over previous
#include <cuda_runtime.h>
#include <cstdint>

#if defined(__CUDA_ARCH_FEAT_SM103_ALL) || defined(__CUDA_ARCH_FEAT_SM100_ALL) || defined(__CUDA_ARCH_FEAT_SM101_ALL)
#define TC_OK 1
#endif

#define TOKENS 4096
#define HIDDEN 2048
#define INTER  768
#define NEXP   64
#define TOPK   8
#define NPAIRS (TOKENS*TOPK)
#define MCAP   2048
#define BK     32
#define STAGE1 65536        // A 32KB + Bg 16KB + Bu 16KB
#define STAGE2 65536        // A 32KB + B 32KB
#define KT1    (HIDDEN/BK)  // 64
#define KT2    (INTER/BK)   // 24
#define WSZ    100663296    // 64*2048*768

__device__ int   g_tc_ok;
__device__ int   g_ok1;
__device__ int   g_ok2;
__device__ int   g_counts[NEXP];
__device__ int   g_offsets[NEXP+1];
__device__ int   g_cursor[NEXP];
__device__ int   g_pair_e[NPAIRS];
__device__ float g_pair_w[NPAIRS];
__device__ int   g_row_token[NPAIRS];
__device__ float g_row_weight[NPAIRS];
__device__ int   g_s2p[NPAIRS];
__device__ float g_act[(size_t)NPAIRS * INTER];
__device__ float g_pout[(size_t)NPAIRS * HIDDEN];
__device__ float g_hid[(size_t)TOKENS * HIDDEN];
__device__ float g_wtg[WSZ];   // gate^T [E][INTER][HIDDEN]
__device__ float g_wtu[WSZ];   // up^T   [E][INTER][HIDDEN]
__device__ float g_wtd[WSZ];   // down^T [E][HIDDEN][INTER]

__device__ __forceinline__ uint32_t smem_u32(const void* p) {
    return (uint32_t)__cvta_generic_to_shared(p);
}
__device__ __forceinline__ float f2tf(float x) {
    uint32_t r;
    asm("cvt.rna.tf32.f32 %0, %1;" : "=r"(r) : "f"(x));
    return __uint_as_float(r);
}
__device__ __forceinline__ uint32_t f2tfu(float x) {
    uint32_t r;
    asm("cvt.rna.tf32.f32 %0, %1;" : "=r"(r) : "f"(x));
    return r;
}
#define SW128(o) ((o) ^ (((o) >> 3) & 0x70))
#define CP16(d, s) asm volatile("cp.async.cg.shared.global [%0], [%1], 16;\n" :: "r"(d), "l"(s))
#define CP_COMMIT  asm volatile("cp.async.commit_group;\n")
#define CP_WAIT(n) asm volatile("cp.async.wait_group %0;\n" :: "n"(n))
#define MBAR_INIT(mb, c) asm volatile("mbarrier.init.shared.b64 [%0], %1;" :: "r"(mb), "r"(c) : "memory")
#define MBAR_WAIT(mb, ph)                                                     \
    asm volatile("{\n\t.reg .pred P1;\n\t"                                    \
        "WL_%=:\n\t"                                                          \
        "mbarrier.try_wait.parity.acquire.cta.shared::cta.b64 P1, [%0], %1, 0x989680;\n\t" \
        "@P1 bra.uni WD_%=;\n\t"                                              \
        "bra.uni WL_%=;\n\t"                                                  \
        "WD_%=:\n\t}" :: "r"(mb), "r"(ph) : "memory")

#ifdef TC_OK
#define TC_ALLOC(sm, n)  asm volatile("tcgen05.alloc.cta_group::1.sync.aligned.shared::cta.b32 [%0], %1;" :: "r"(sm), "r"(n) : "memory")
#define TC_DEALLOC(t, n) asm volatile("tcgen05.dealloc.cta_group::1.sync.aligned.b32 %0, %1;" :: "r"(t), "r"(n))
#define TC_RELINQ()      asm volatile("tcgen05.relinquish_alloc_permit.cta_group::1.sync.aligned;")
#define TC_COMMIT(mb)    asm volatile("tcgen05.commit.cta_group::1.mbarrier::arrive::one.shared::cluster.b64 [%0];" :: "r"(mb) : "memory")
#define TC_FENCE_AFTER() asm volatile("tcgen05.fence::after_thread_sync;" ::: "memory")
#define TC_WAIT_LD()     asm volatile("tcgen05.wait::ld.sync.aligned;" ::: "memory")
#define FENCE_ASYNC()    asm volatile("fence.proxy.async.shared::cta;" ::: "memory")
#define LDTM_X32(r, a)                                                        \
    asm volatile("tcgen05.ld.sync.aligned.32x32b.x32.b32 "                    \
        "{%0,%1,%2,%3,%4,%5,%6,%7,%8,%9,%10,%11,%12,%13,%14,%15,"             \
        "%16,%17,%18,%19,%20,%21,%22,%23,%24,%25,%26,%27,%28,%29,%30,%31},[%32];" \
        : "=r"((r)[0]),"=r"((r)[1]),"=r"((r)[2]),"=r"((r)[3]),                \
          "=r"((r)[4]),"=r"((r)[5]),"=r"((r)[6]),"=r"((r)[7]),                \
          "=r"((r)[8]),"=r"((r)[9]),"=r"((r)[10]),"=r"((r)[11]),              \
          "=r"((r)[12]),"=r"((r)[13]),"=r"((r)[14]),"=r"((r)[15]),            \
          "=r"((r)[16]),"=r"((r)[17]),"=r"((r)[18]),"=r"((r)[19]),            \
          "=r"((r)[20]),"=r"((r)[21]),"=r"((r)[22]),"=r"((r)[23]),            \
          "=r"((r)[24]),"=r"((r)[25]),"=r"((r)[26]),"=r"((r)[27]),            \
          "=r"((r)[28]),"=r"((r)[29]),"=r"((r)[30]),"=r"((r)[31]) : "r"(a))

__device__ __forceinline__ uint64_t desc_k(uint32_t a) {   // K-major SW128
    return (uint64_t(2) << 61) | (uint64_t(1) << 46) | (uint64_t(64) << 32) |
           (uint64_t(1) << 16) | ((uint64_t)(a >> 4) & 0x3FFF);
}
// d=f32, a=b=tf32, K-major, M=128
#define IDESC32 ((1u<<4)|(2u<<7)|(2u<<10)|(4u<<17)|(8u<<24))   // N=32 (selftest)
#define IDESC64 ((1u<<4)|(2u<<7)|(2u<<10)|(8u<<17)|(8u<<24))   // N=64 (gemms)
__device__ __forceinline__ void mma_n32(uint32_t d, uint64_t ad, uint64_t bd, uint32_t acc) {
    asm volatile(
        "{\n\t.reg .pred p;\n\tsetp.ne.u32 p, %4, 0;\n\t"
        "tcgen05.mma.cta_group::1.kind::tf32 [%0], %1, %2, %3, {%5,%5,%5,%5}, p;\n\t}"
        :: "r"(d), "l"(ad), "l"(bd), "r"(IDESC32), "r"(acc), "r"(0u) : "memory");
}
__device__ __forceinline__ void mma_n64(uint32_t d, uint64_t ad, uint64_t bd, uint32_t acc) {
    asm volatile(
        "{\n\t.reg .pred p;\n\tsetp.ne.u32 p, %4, 0;\n\t"
        "tcgen05.mma.cta_group::1.kind::tf32 [%0], %1, %2, %3, {%5,%5,%5,%5}, p;\n\t}"
        :: "r"(d), "l"(ad), "l"(bd), "r"(IDESC64), "r"(acc), "r"(0u) : "memory");
}
#endif

// ---------------- self-test ----------------
__device__ __forceinline__ float tva(int m, int k) {
    return f2tf(0.01f * (float)((m * 7 + k * 13) % 31 - 15));
}
__device__ __forceinline__ float tvb(int n, int k) {
    return f2tf(0.02f * (float)((n * 5 + k * 3) % 29 - 14));
}
__global__ void selftest_kernel() {
#ifdef TC_OK
    __shared__ __align__(1024) float sma[4096];
    __shared__ __align__(1024) float smb[1024];
    __shared__ uint32_t s_tmem[1];
    __shared__ __align__(8) uint64_t s_mbar[1];
    __shared__ float s_d, s_r;
    int tid = threadIdx.x, wid = tid >> 5, lane = tid & 31;

    if (wid == 0) { TC_ALLOC(smem_u32(s_tmem), 128); TC_RELINQ(); }
    if (tid == 0) { MBAR_INIT(smem_u32(s_mbar), 1); s_d = 0.f; s_r = 0.f; }
    for (int idx = tid; idx < 4096; idx += 128) {
        int m = idx >> 5, k = idx & 31;
        *(float*)((char*)sma + SW128((uint32_t)(m * 128 + k * 4))) = tva(m, k);
    }
    for (int idx = tid; idx < 1024; idx += 128) {
        int n = idx >> 5, k = idx & 31;
        *(float*)((char*)smb + SW128((uint32_t)(n * 128 + k * 4))) = tvb(n, k);
    }
    __syncthreads();
    uint32_t tmem = s_tmem[0], mb = smem_u32(s_mbar);
    if (tid == 0) {
        FENCE_ASYNC();
        uint64_t ad = desc_k(smem_u32(sma)), bd = desc_k(smem_u32(smb));
#pragma unroll
        for (int ks = 0; ks < 4; ++ks)
            mma_n32(tmem, ad + ks * 2, bd + ks * 2, ks > 0 ? 1u : 0u);
        TC_COMMIT(mb);
    }
    __syncthreads();
    MBAR_WAIT(mb, 0);
    TC_FENCE_AFTER();

    uint32_t r[32];
    LDTM_X32(r, tmem);
    TC_WAIT_LD();
    int m = wid * 32 + lane;
    float d = 0.f, rf = 0.f;
#pragma unroll 4
    for (int n = 0; n < 32; ++n) {
        float ref = 0.f;
        for (int k = 0; k < 32; ++k) ref += tva(m, k) * tvb(n, k);
        d  += fabsf(__uint_as_float(r[n]) - ref);
        rf += fabsf(ref);
    }
    atomicAdd(&s_d, d); atomicAdd(&s_r, rf);
    __syncthreads();
    if (tid == 0) g_tc_ok = (s_d <= 0.01f * s_r + 1e-3f) ? 1 : 0;
    __syncthreads();
    if (wid == 0) TC_DEALLOC(tmem, 128);
#else
    if (threadIdx.x == 0) g_tc_ok = 0;
#endif
}

// ---------------- prep ----------------
__global__ void rnd_kernel(const float4* __restrict__ src, float4* __restrict__ dst, int n4) {
    int i = blockIdx.x * blockDim.x + threadIdx.x, st = gridDim.x * blockDim.x;
    for (; i < n4; i += st) {
        float4 v = src[i];
        v.x = f2tf(v.x); v.y = f2tf(v.y); v.z = f2tf(v.z); v.w = f2tf(v.w);
        dst[i] = v;
    }
}
// W[e][K][N] -> WT[e][N][K], tf32-rounded, float4 both directions
__global__ void transpose_kernel(const float* __restrict__ src, float* __restrict__ dst,
                                 int K, int N) {
    if (g_tc_ok == 0) return;
    __shared__ float t[32][33];
    int e = blockIdx.z;
    int k0 = blockIdx.x * 32, n0 = blockIdx.y * 32;
    int r = threadIdx.x >> 3, c4 = (threadIdx.x & 7) << 2;
    float4 v = *(const float4*)(src + ((size_t)e * K + k0 + r) * N + n0 + c4);
    t[r][c4] = v.x; t[r][c4 + 1] = v.y; t[r][c4 + 2] = v.z; t[r][c4 + 3] = v.w;
    __syncthreads();
    float4 o;
    o.x = f2tf(t[c4    ][r]);
    o.y = f2tf(t[c4 + 1][r]);
    o.z = f2tf(t[c4 + 2][r]);
    o.w = f2tf(t[c4 + 3][r]);
    *(float4*)(dst + ((size_t)e * N + n0 + r) * K + k0 + c4) = o;
}
__global__ void init_kernel() { if (threadIdx.x < NEXP) g_counts[threadIdx.x] = 0; }

__global__ void route_kernel(const float* __restrict__ logits) {
    int t = blockIdx.x * blockDim.x + threadIdx.x;
    if (t >= TOKENS) return;
    float l[NEXP];
    const float* lp = logits + (size_t)t * NEXP;
#pragma unroll
    for (int i = 0; i < NEXP; ++i) l[i] = lp[i];
    float val[TOPK]; int sel[TOPK];
#pragma unroll
    for (int k = 0; k < TOPK; ++k) {
        float best = -1e30f; int bi = 0;
#pragma unroll
        for (int i = 0; i < NEXP; ++i)
            if (l[i] > best) { best = l[i]; bi = i; }
        val[k] = best; sel[k] = bi; l[bi] = -1e30f;
    }
    float m = val[0], s = 0.f, w[TOPK];
#pragma unroll
    for (int k = 0; k < TOPK; ++k) { w[k] = __expf(val[k] - m); s += w[k]; }
    float inv = 1.f / s;
#pragma unroll
    for (int k = 0; k < TOPK; ++k) {
        g_pair_e[t * TOPK + k] = sel[k];
        g_pair_w[t * TOPK + k] = w[k] * inv;
        atomicAdd(&g_counts[sel[k]], 1);
    }
}
__global__ void scan_kernel() {
    if (threadIdx.x == 0) {
        int acc = 0;
        for (int e = 0; e < NEXP; ++e) { g_offsets[e] = acc; g_cursor[e] = acc; acc += g_counts[e]; }
        g_offsets[NEXP] = acc;
    }
}
__global__ void scatter_kernel() {
    int p = blockIdx.x * blockDim.x + threadIdx.x;
    if (p >= NPAIRS) return;
    int slot = atomicAdd(&g_cursor[g_pair_e[p]], 1);
    g_row_token[slot]  = p >> 3;
    g_row_weight[slot] = g_pair_w[p];
    g_s2p[slot] = p;
}

// ================= tcgen05 GEMM1: M=256, N=128 (gate+up), 3-stage =========
__global__ void __launch_bounds__(256, 1)
gemm1_tc() {
#ifdef TC_OK
    if (g_tc_ok == 0) return;
    int e = blockIdx.z;
    int off = g_offsets[e], cnt = g_offsets[e + 1] - off;
    int m0 = blockIdx.x * 256;
    if (m0 >= cnt) return;
    int n0 = blockIdx.y * 128;

    extern __shared__ char dyn[];
    uint32_t sbase = (smem_u32(dyn) + 1023u) & ~1023u;
    __shared__ uint32_t s_tmem[1];
    __shared__ __align__(8) uint64_t s_mbar[3];
    int tid = threadIdx.x, wid = tid >> 5, lane = tid & 31;

    if (wid == 0) { TC_ALLOC(smem_u32(s_tmem), 512); TC_RELINQ(); }
    if (tid == 0) {
        MBAR_INIT(smem_u32(&s_mbar[0]), 1);
        MBAR_INIT(smem_u32(&s_mbar[1]), 1);
        MBAR_INIT(smem_u32(&s_mbar[2]), 1);
    }
    __syncthreads();
    uint32_t tmem = s_tmem[0];
    uint32_t mbar[3] = { smem_u32(&s_mbar[0]), smem_u32(&s_mbar[1]), smem_u32(&s_mbar[2]) };

    const size_t wb = (size_t)e * HIDDEN * INTER;
    int maxslot = off + cnt - 1;
    const float* asrc[8]; uint32_t aoff[8];
    const float* gsrc[4]; const float* usrc[4]; uint32_t boff[4];
#pragma unroll
    for (int j = 0; j < 8; ++j) {
        int id = tid + j * 256;
        int row = id >> 3, c = id & 7;
        int slot = off + m0 + row; if (slot > maxslot) slot = maxslot;
        asrc[j] = g_hid + (size_t)g_row_token[slot] * HIDDEN + c * 4;
        aoff[j] = SW128((uint32_t)(row * 128 + c * 16));
    }
#pragma unroll
    for (int j = 0; j < 4; ++j) {
        int id = tid + j * 256;
        int nrow = id >> 3, c = id & 7;
        gsrc[j] = g_wtg + wb + (size_t)(n0 + nrow) * HIDDEN + c * 4;
        usrc[j] = g_wtu + wb + (size_t)(n0 + nrow) * HIDDEN + c * 4;
        boff[j] = SW128((uint32_t)(nrow * 128 + c * 16));
    }
    auto load_tile = [&](int s, int k0) {
        uint32_t sb = sbase + s * STAGE1;
#pragma unroll
        for (int j = 0; j < 8; ++j) CP16(sb + aoff[j], asrc[j] + k0);
#pragma unroll
        for (int j = 0; j < 4; ++j) CP16(sb + 32768u + boff[j], gsrc[j] + k0);
#pragma unroll
        for (int j = 0; j < 4; ++j) CP16(sb + 49152u + boff[j], usrc[j] + k0);
    };

    load_tile(0, 0);  CP_COMMIT;
    load_tile(1, BK); CP_COMMIT;
    for (int kt = 0; kt < KT1; ++kt) {
        int s = kt % 3;
        if (kt < KT1 - 1) { CP_WAIT(1); } else { CP_WAIT(0); }
        __syncthreads();
        if (tid == 0) {
            FENCE_ASYNC();
            uint32_t sb = sbase + s * STAGE1;
            uint64_t ad = desc_k(sb);
            uint64_t bg = desc_k(sb + 32768u), bu = desc_k(sb + 49152u);
#pragma unroll
            for (int ks = 0; ks < 4; ++ks) {
                uint32_t acc = (kt > 0 || ks > 0) ? 1u : 0u;
#pragma unroll
                for (int mh = 0; mh < 2; ++mh) {
                    uint64_t am = ad + mh * 1024 + ks * 2;   // m-half A: +16KB
#pragma unroll
                    for (int j = 0; j < 2; ++j) {
                        mma_n64(tmem + mh * 256 + j * 64,       am, bg + j * 512 + ks * 2, acc);
                        mma_n64(tmem + mh * 256 + 128 + j * 64, am, bu + j * 512 + ks * 2, acc);
                    }
                }
            }
            TC_COMMIT(mbar[s]);
        }
        if (kt + 2 < KT1) {
            if (kt >= 1)
                MBAR_WAIT(mbar[(kt - 1) % 3], ((kt - 1) / 3) & 1);  // MMA(kt-1) done
            load_tile((kt + 2) % 3, (kt + 2) * BK); CP_COMMIT;
        }
    }
    MBAR_WAIT(mbar[(KT1 - 1) % 3], ((KT1 - 1) / 3) & 1);
    TC_FENCE_AFTER();

    int mh = wid >> 2, sp = wid & 3;
    int row = mh * 128 + sp * 32 + lane;
    bool valid = (m0 + row) < cnt;
    float* dst = g_act + (size_t)(off + m0 + row) * INTER + n0;
    uint32_t tb = tmem + mh * 256;
#pragma unroll
    for (int cb = 0; cb < 4; ++cb) {
        int c0 = cb * 32;
        uint32_t rg[32], ru[32];
        LDTM_X32(rg, tb + c0);
        LDTM_X32(ru, tb + 128 + c0);
        TC_WAIT_LD();
        if (valid) {
#pragma unroll
            for (int i = 0; i < 32; i += 4) {
                float4 v;
#pragma unroll
                for (int q = 0; q < 4; ++q) {
                    float g = __uint_as_float(rg[i + q]);
                    float u = __uint_as_float(ru[i + q]);
                    ((float*)&v)[q] = f2tf(g / (1.f + __expf(-g)) * u);
                }
                *(float4*)(dst + c0 + i) = v;
            }
        }
    }
    __syncthreads();
    if (wid == 0) TC_DEALLOC(tmem, 512);
#endif
}

// ================= tcgen05 GEMM2: M=256, N=256, 3-stage =================
__global__ void __launch_bounds__(256, 1)
gemm2_tc() {
#ifdef TC_OK
    if (g_ok1 == 0) return;
    int e = blockIdx.z;
    int off = g_offsets[e], cnt = g_offsets[e + 1] - off;
    int m0 = blockIdx.x * 256;
    if (m0 >= cnt) return;
    int n0 = blockIdx.y * 256;

    extern __shared__ char dyn[];
    uint32_t sbase = (smem_u32(dyn) + 1023u) & ~1023u;
    __shared__ uint32_t s_tmem[1];
    __shared__ __align__(8) uint64_t s_mbar[3];
    int tid = threadIdx.x, wid = tid >> 5, lane = tid & 31;

    if (wid == 0) { TC_ALLOC(smem_u32(s_tmem), 512); TC_RELINQ(); }
    if (tid == 0) {
        MBAR_INIT(smem_u32(&s_mbar[0]), 1);
        MBAR_INIT(smem_u32(&s_mbar[1]), 1);
        MBAR_INIT(smem_u32(&s_mbar[2]), 1);
    }
    __syncthreads();
    uint32_t tmem = s_tmem[0];
    uint32_t mbar[3] = { smem_u32(&s_mbar[0]), smem_u32(&s_mbar[1]), smem_u32(&s_mbar[2]) };

    const size_t wb = (size_t)e * INTER * HIDDEN;
    const float* asrc[8]; uint32_t aoff[8];
    const float* bsrc[8]; uint32_t boff[8];
#pragma unroll
    for (int j = 0; j < 8; ++j) {
        int id = tid + j * 256;
        int row = id >> 3, c = id & 7;
        int ar = off + m0 + row; if (ar > NPAIRS - 1) ar = NPAIRS - 1;
        asrc[j] = g_act + (size_t)ar * INTER + c * 4;
        aoff[j] = SW128((uint32_t)(row * 128 + c * 16));
        bsrc[j] = g_wtd + wb + (size_t)(n0 + row) * INTER + c * 4;
        boff[j] = aoff[j];
    }
    auto load_tile = [&](int s, int k0) {
        uint32_t sb = sbase + s * STAGE2;
#pragma unroll
        for (int j = 0; j < 8; ++j) CP16(sb + aoff[j], asrc[j] + k0);
#pragma unroll
        for (int j = 0; j < 8; ++j) CP16(sb + 32768u + boff[j], bsrc[j] + k0);
    };

    load_tile(0, 0);  CP_COMMIT;
    load_tile(1, BK); CP_COMMIT;
    for (int kt = 0; kt < KT2; ++kt) {
        int s = kt % 3;
        if (kt < KT2 - 1) { CP_WAIT(1); } else { CP_WAIT(0); }
        __syncthreads();
        if (tid == 0) {
            FENCE_ASYNC();
            uint32_t sb = sbase + s * STAGE2;
            uint64_t ad = desc_k(sb);
            uint64_t bd = desc_k(sb + 32768u);
#pragma unroll
            for (int ks = 0; ks < 4; ++ks) {
                uint32_t acc = (kt > 0 || ks > 0) ? 1u : 0u;
#pragma unroll
                for (int mh = 0; mh < 2; ++mh) {
                    uint64_t am = ad + mh * 1024 + ks * 2;
#pragma unroll
                    for (int j = 0; j < 4; ++j)
                        mma_n64(tmem + mh * 256 + j * 64, am, bd + j * 512 + ks * 2, acc);
                }
            }
            TC_COMMIT(mbar[s]);
        }
        if (kt + 2 < KT2) {
            if (kt >= 1)
                MBAR_WAIT(mbar[(kt - 1) % 3], ((kt - 1) / 3) & 1);
            load_tile((kt + 2) % 3, (kt + 2) * BK); CP_COMMIT;
        }
    }
    MBAR_WAIT(mbar[(KT2 - 1) % 3], ((KT2 - 1) / 3) & 1);
    TC_FENCE_AFTER();

    int mh = wid >> 2, sp = wid & 3;
    int row = mh * 128 + sp * 32 + lane;
    bool valid = (m0 + row) < cnt;
    int slot = off + m0 + row; if (slot > NPAIRS - 1) slot = NPAIRS - 1;
    float w = g_row_weight[slot];
    float* dst = g_pout + (size_t)g_s2p[slot] * HIDDEN + n0;
    uint32_t tb = tmem + mh * 256;
#pragma unroll
    for (int cb = 0; cb < 8; ++cb) {
        int c0 = cb * 32;
        uint32_t r[32];
        LDTM_X32(r, tb + c0);
        TC_WAIT_LD();
        if (valid) {
#pragma unroll
            for (int i = 0; i < 32; i += 4) {
                float4 v;
                ((float*)&v)[0] = __uint_as_float(r[i])     * w;
                ((float*)&v)[1] = __uint_as_float(r[i + 1]) * w;
                ((float*)&v)[2] = __uint_as_float(r[i + 2]) * w;
                ((float*)&v)[3] = __uint_as_float(r[i + 3]) * w;
                *(float4*)(dst + c0 + i) = v;
            }
        }
    }
    __syncthreads();
    if (wid == 0) TC_DEALLOC(tmem, 512);
#endif
}

// ---------------- verifiers ----------------
__global__ void verify1_kernel() {
    if (g_tc_ok == 0) { if (threadIdx.x == 0) g_ok1 = 0; return; }
    int j = threadIdx.x * 24;
    int e = 0;
    while (g_offsets[e + 1] < 1) ++e;
    int tok = g_row_token[0];
    const float* h  = g_hid + (size_t)tok * HIDDEN;
    const float* wg = g_wtg + (size_t)e * HIDDEN * INTER + (size_t)j * HIDDEN;
    const float* wu = g_wtu + (size_t)e * HIDDEN * INTER + (size_t)j * HIDDEN;
    float ag = 0.f, au = 0.f;
    for (int k = 0; k < HIDDEN; ++k) { ag += h[k] * wg[k]; au += h[k] * wu[k]; }
    float ref = f2tf(ag / (1.f + expf(-ag)) * au);
    float d = fabsf(g_act[j] - ref), r = fabsf(ref);
#pragma unroll
    for (int o = 16; o; o >>= 1) {
        d += __shfl_xor_sync(~0u, d, o);
        r += __shfl_xor_sync(~0u, r, o);
    }
    if (threadIdx.x == 0) g_ok1 = (d <= 0.02f * r + 1e-2f) ? 1 : 0;
}
__global__ void verify2_kernel() {
    if (g_ok1 == 0) { if (threadIdx.x == 0) g_ok2 = 0; return; }
    int n = threadIdx.x * 64;
    int e = 0;
    while (g_offsets[e + 1] < 1) ++e;
    int p = g_s2p[0];
    float w = g_row_weight[0];
    const float* a  = g_act;
    const float* wd = g_wtd + (size_t)e * INTER * HIDDEN + (size_t)n * INTER;
    float acc = 0.f;
    for (int k = 0; k < INTER; ++k) acc += a[k] * wd[k];
    float ref = acc * w;
    float d = fabsf(g_pout[(size_t)p * HIDDEN + n] - ref), r = fabsf(ref);
#pragma unroll
    for (int o = 16; o; o >>= 1) {
        d += __shfl_xor_sync(~0u, d, o);
        r += __shfl_xor_sync(~0u, r, o);
    }
    if (threadIdx.x == 0) g_ok2 = (d <= 0.02f * r + 1e-2f) ? 1 : 0;
}

// ================= legacy mma.sync fallback =================
#define MMA_TF32(c, a, b)                                                     \
    asm volatile(                                                             \
        "mma.sync.aligned.m16n8k8.row.col.f32.tf32.tf32.f32 "                 \
        "{%0,%1,%2,%3},{%4,%5,%6,%7},{%8,%9},{%0,%1,%2,%3};"                  \
        : "+f"((c)[0]), "+f"((c)[1]), "+f"((c)[2]), "+f"((c)[3])              \
        : "r"((a)[0]), "r"((a)[1]), "r"((a)[2]), "r"((a)[3]),                 \
          "r"((b)[0]), "r"((b)[1]))

__global__ void __launch_bounds__(256, 2)
gemm1_legacy(const float* __restrict__ gate_w, const float* __restrict__ up_w) {
    if (g_ok1) return;
    int e = blockIdx.z;
    int off = g_offsets[e], cnt = g_offsets[e + 1] - off;
    int m0 = blockIdx.x * 128;
    if (m0 >= cnt) return;
    int n0 = blockIdx.y * 64;

    __shared__ float sA [2][128][20];
    __shared__ float sBg[2][16][68];
    __shared__ float sBu[2][16][68];

    int tid = threadIdx.x;
    const size_t wbase = (size_t)e * HIDDEN * INTER;
    int maxslot = off + cnt - 1;

    const float* asrc[2]; int arowi[2], akc[2];
#pragma unroll
    for (int j = 0; j < 2; ++j) {
        int c = tid + j * 256;
        int row = c >> 2, kc = (c & 3) << 2;
        int slot = off + m0 + row; if (slot > maxslot) slot = maxslot;
        asrc[j] = g_hid + (size_t)g_row_token[slot] * HIDDEN + kc;
        arowi[j] = row; akc[j] = kc;
    }
    int bkr = tid >> 4, bnc = (tid & 15) << 2;
    const float* gsrc = gate_w + wbase + (size_t)bkr * INTER + n0 + bnc;
    const float* usrc = up_w   + wbase + (size_t)bkr * INTER + n0 + bnc;

    auto load_tile = [&](int s, int k0) {
#pragma unroll
        for (int j = 0; j < 2; ++j)
            CP16(smem_u32(&sA[s][arowi[j]][akc[j]]), asrc[j] + k0);
        CP16(smem_u32(&sBg[s][bkr][bnc]), gsrc + (size_t)k0 * INTER);
        CP16(smem_u32(&sBu[s][bkr][bnc]), usrc + (size_t)k0 * INTER);
    };

    float cg[2][4][4] = {}, cu[2][4][4] = {};
    int warp = tid >> 5, lane = tid & 31;
    int wm = warp >> 1, wn = warp & 1;
    int gid = lane >> 2, tig = lane & 3;

    load_tile(0, 0); CP_COMMIT;
    const int KT = HIDDEN / 16;
    for (int kt = 0; kt < KT; ++kt) {
        int s = kt & 1;
        if (kt + 1 < KT) { load_tile(s ^ 1, (kt + 1) * 16); CP_COMMIT; CP_WAIT(1); }
        else             { CP_WAIT(0); }
        __syncthreads();
#pragma unroll
        for (int ks = 0; ks < 2; ++ks) {
            int k8 = ks * 8;
            uint32_t af[2][4];
#pragma unroll
            for (int mt = 0; mt < 2; ++mt) {
                int r = wm * 32 + mt * 16;
                af[mt][0] = f2tfu(sA[s][r + gid    ][k8 + tig    ]);
                af[mt][1] = f2tfu(sA[s][r + gid + 8][k8 + tig    ]);
                af[mt][2] = f2tfu(sA[s][r + gid    ][k8 + tig + 4]);
                af[mt][3] = f2tfu(sA[s][r + gid + 8][k8 + tig + 4]);
            }
            uint32_t bg[4][2], bu[4][2];
#pragma unroll
            for (int nt = 0; nt < 4; ++nt) {
                int cix = wn * 32 + nt * 8 + gid;
                bg[nt][0] = f2tfu(sBg[s][k8 + tig    ][cix]);
                bg[nt][1] = f2tfu(sBg[s][k8 + tig + 4][cix]);
                bu[nt][0] = f2tfu(sBu[s][k8 + tig    ][cix]);
                bu[nt][1] = f2tfu(sBu[s][k8 + tig + 4][cix]);
            }
#pragma unroll
            for (int mt = 0; mt < 2; ++mt)
#pragma unroll
                for (int nt = 0; nt < 4; ++nt) {
                    MMA_TF32(cg[mt][nt], af[mt], bg[nt]);
                    MMA_TF32(cu[mt][nt], af[mt], bu[nt]);
                }
        }
        __syncthreads();
    }
#pragma unroll
    for (int mt = 0; mt < 2; ++mt) {
#pragma unroll
        for (int i = 0; i < 4; ++i) {
            int row  = wm * 32 + mt * 16 + gid + ((i >> 1) << 3);
            int srow = m0 + row;
            if (srow >= cnt) continue;
            size_t base = (size_t)(off + srow) * INTER + n0 + wn * 32;
#pragma unroll
            for (int nt = 0; nt < 4; ++nt) {
                float g = cg[mt][nt][i], u = cu[mt][nt][i];
                g_act[base + nt * 8 + 2 * tig + (i & 1)] = f2tf(g / (1.f + __expf(-g)) * u);
            }
        }
    }
}

__global__ void __launch_bounds__(256, 2)
gemm2_legacy(const float* __restrict__ down_w) {
    if (g_ok2) return;
    int e = blockIdx.z;
    int off = g_offsets[e], cnt = g_offsets[e + 1] - off;
    int m0 = blockIdx.x * 128;
    if (m0 >= cnt) return;
    int n0 = blockIdx.y * 128;

    __shared__ float sA[2][128][20];
    __shared__ float sB[2][16][132];

    int tid = threadIdx.x;
    const size_t wbase = (size_t)e * INTER * HIDDEN;

    const float* asrc[2]; int arowi[2], akc[2];
#pragma unroll
    for (int j = 0; j < 2; ++j) {
        int c = tid + j * 256;
        int row = c >> 2, kc = (c & 3) << 2;
        int ar = off + m0 + row; if (ar > NPAIRS - 1) ar = NPAIRS - 1;
        asrc[j] = g_act + (size_t)ar * INTER + kc;
        arowi[j] = row; akc[j] = kc;
    }
    const float* bsrc[2]; int bkri[2], bnci[2];
#pragma unroll
    for (int j = 0; j < 2; ++j) {
        int c = tid + j * 256;
        int kr = c >> 5, nc = (c & 31) << 2;
        bsrc[j] = down_w + wbase + (size_t)kr * HIDDEN + n0 + nc;
        bkri[j] = kr; bnci[j] = nc;
    }
    auto load_tile = [&](int s, int k0) {
#pragma unroll
        for (int j = 0; j < 2; ++j)
            CP16(smem_u32(&sA[s][arowi[j]][akc[j]]), asrc[j] + k0);
#pragma unroll
        for (int j = 0; j < 2; ++j)
            CP16(smem_u32(&sB[s][bkri[j]][bnci[j]]), bsrc[j] + (size_t)k0 * HIDDEN);
    };

    float acc[2][8][4] = {};
    int warp = tid >> 5, lane = tid & 31;
    int wm = warp >> 1, wn = warp & 1;
    int gid = lane >> 2, tig = lane & 3;

    load_tile(0, 0); CP_COMMIT;
    const int KT = INTER / 16;
    for (int kt = 0; kt < KT; ++kt) {
        int s = kt & 1;
        if (kt + 1 < KT) { load_tile(s ^ 1, (kt + 1) * 16); CP_COMMIT; CP_WAIT(1); }
        else             { CP_WAIT(0); }
        __syncthreads();
#pragma unroll
        for (int ks = 0; ks < 2; ++ks) {
            int k8 = ks * 8;
            uint32_t af[2][4];
#pragma unroll
            for (int mt = 0; mt < 2; ++mt) {
                int r = wm * 32 + mt * 16;
                af[mt][0] = f2tfu(sA[s][r + gid    ][k8 + tig    ]);
                af[mt][1] = f2tfu(sA[s][r + gid + 8][k8 + tig    ]);
                af[mt][2] = f2tfu(sA[s][r + gid    ][k8 + tig + 4]);
                af[mt][3] = f2tfu(sA[s][r + gid + 8][k8 + tig + 4]);
            }
            uint32_t bf[8][2];
#pragma unroll
            for (int nt = 0; nt < 8; ++nt) {
                int cix = wn * 64 + nt * 8 + gid;
                bf[nt][0] = f2tfu(sB[s][k8 + tig    ][cix]);
                bf[nt][1] = f2tfu(sB[s][k8 + tig + 4][cix]);
            }
#pragma unroll
            for (int mt = 0; mt < 2; ++mt)
#pragma unroll
                for (int nt = 0; nt < 8; ++nt)
                    MMA_TF32(acc[mt][nt], af[mt], bf[nt]);
        }
        __syncthreads();
    }
#pragma unroll
    for (int mt = 0; mt < 2; ++mt) {
#pragma unroll
        for (int i = 0; i < 4; ++i) {
            int row  = wm * 32 + mt * 16 + gid + ((i >> 1) << 3);
            int srow = m0 + row;
            if (srow >= cnt) continue;
            int slot = off + srow;
            float w  = g_row_weight[slot];
            float* orow = g_pout + (size_t)g_s2p[slot] * HIDDEN + n0 + wn * 64;
#pragma unroll
            for (int nt = 0; nt < 8; ++nt)
                orow[nt * 8 + 2 * tig + (i & 1)] = acc[mt][nt][i] * w;
        }
    }
}

// ---------------- combine ----------------
__global__ void combine_kernel(float* __restrict__ out) {
    int t = blockIdx.x, c = threadIdx.x;
    const float* base = g_pout + (size_t)t * TOPK * HIDDEN + c * 4;
    float4 acc = make_float4(0.f, 0.f, 0.f, 0.f);
#pragma unroll
    for (int k = 0; k < TOPK; ++k) {
        float4 v = *(const float4*)(base + (size_t)k * HIDDEN);
        acc.x += v.x; acc.y += v.y; acc.z += v.z; acc.w += v.w;
    }
    *(float4*)(out + (size_t)t * HIDDEN + c * 4) = acc;
}

// ---------------- launch ----------------
extern "C" void kernel_launch(void* const* d_in, const int* in_sizes, int n_in,
                              void* d_out, int out_size) {
    const float* hidden = (const float*)d_in[0];
    const float* logits = (const float*)d_in[1];
    const float* gate   = (const float*)d_in[2];
    const float* up     = (const float*)d_in[3];
    const float* down   = (const float*)d_in[4];
    float* out = (float*)d_out;

    cudaFuncSetAttribute(gemm1_tc, cudaFuncAttributeMaxDynamicSharedMemorySize, 3 * STAGE1 + 1024);
    cudaFuncSetAttribute(gemm2_tc, cudaFuncAttributeMaxDynamicSharedMemorySize, 3 * STAGE2 + 1024);

    float *wtg, *wtu, *wtd, *rh;
    cudaGetSymbolAddress((void**)&wtg, g_wtg);
    cudaGetSymbolAddress((void**)&wtu, g_wtu);
    cudaGetSymbolAddress((void**)&wtd, g_wtd);
    cudaGetSymbolAddress((void**)&rh,  g_hid);

    selftest_kernel <<<1, 128>>>();
    rnd_kernel      <<<2048, 512>>>((const float4*)hidden, (float4*)rh, TOKENS * HIDDEN / 4);
    transpose_kernel<<<dim3(HIDDEN / 32, INTER / 32, NEXP), 256>>>(gate, wtg, HIDDEN, INTER);
    transpose_kernel<<<dim3(HIDDEN / 32, INTER / 32, NEXP), 256>>>(up,   wtu, HIDDEN, INTER);
    transpose_kernel<<<dim3(INTER / 32, HIDDEN / 32, NEXP), 256>>>(down, wtd, INTER, HIDDEN);
    init_kernel     <<<1, 64>>>();
    route_kernel    <<<TOKENS / 256, 256>>>(logits);
    scan_kernel     <<<1, 32>>>();
    scatter_kernel  <<<NPAIRS / 256, 256>>>();
    gemm1_tc        <<<dim3(MCAP / 256, INTER / 128, NEXP), 256, 3 * STAGE1 + 1024>>>();
    verify1_kernel  <<<1, 32>>>();
    gemm1_legacy    <<<dim3(MCAP / 128, INTER / 64,  NEXP), 256>>>(gate, up);
    gemm2_tc        <<<dim3(MCAP / 256, HIDDEN / 256, NEXP), 256, 3 * STAGE2 + 1024>>>();
    verify2_kernel  <<<1, 32>>>();
    gemm2_legacy    <<<dim3(MCAP / 128, HIDDEN / 128, NEXP), 256>>>(down);
    combine_kernel  <<<TOKENS, 512>>>(out);
}